// round 9
// baseline (speedup 1.0000x reference)
#include <cuda_runtime.h>
#include <cuda_bf16.h>
#include <math.h>

#define N_Q   4098
#define N_KV  4099
#define CDIM  384
#define HEADS 6
#define HDIM  64
#define NQTILES 33
#define NITEMS (NQTILES * HEADS)    // 198 attention work items

// ---------------- scratch (device globals; allocation-free) ----------------
__device__ __align__(16) float g_pp[64 * CDIM];     // pooling partials
__device__ float  g_cntp[64];                       // count partials
__device__ __align__(16) float g_back[CDIM];        // back token
__device__ int    g_idx[N_KV];                      // kept key -> source row
__device__ int    g_M;                              // number of kept keys
__device__ int    g_work;                           // attention work counter
__device__ __align__(16) float g_q[N_Q * CDIM];     // tf32-prerounded, prescaled 1/8
__device__ __align__(16) float g_k[N_KV * CDIM];    // tf32-prerounded
__device__ __align__(16) float g_v[N_KV * CDIM];    // tf32-prerounded
__device__ __align__(16) float g_o[N_Q * CDIM];

// ---------------- helpers ---------------------------------------------------
__device__ __forceinline__ unsigned f2tf(float x)
{
    unsigned r;
    asm("cvt.rna.tf32.f32 %0, %1;" : "=r"(r) : "f"(x));
    return r;
}

__device__ __forceinline__ void mma8(float* c, const unsigned* a, const unsigned* b)
{
    asm volatile(
        "mma.sync.aligned.m16n8k8.row.col.f32.tf32.tf32.f32 "
        "{%0,%1,%2,%3}, {%4,%5,%6,%7}, {%8,%9}, {%0,%1,%2,%3};\n"
        : "+f"(c[0]), "+f"(c[1]), "+f"(c[2]), "+f"(c[3])
        : "r"(a[0]), "r"(a[1]), "r"(a[2]), "r"(a[3]), "r"(b[0]), "r"(b[1]));
}

__device__ __forceinline__ void cp16(unsigned dst, const void* src, int sz)
{
    asm volatile("cp.async.ca.shared.global [%0], [%1], 16, %2;"
                 :: "r"(dst), "l"(src), "r"(sz));
}
#define CP_COMMIT() asm volatile("cp.async.commit_group;")
#define CP_WAIT(n)  asm volatile("cp.async.wait_group %0;" :: "n"(n))

// ---------------- 1) background pooling (deterministic, 2-stage) -----------
__global__ void pool_kernel(const float* __restrict__ x, const float* __restrict__ mask)
{
    const int c  = threadIdx.x;            // 384 threads
    const int n0 = blockIdx.x * 64;
    float s = 0.f;
#pragma unroll 8
    for (int i = 0; i < 64; i++) {
        const int n = n0 + i;
        const float rev = (mask[n] < 0.5f) ? 1.f : 0.f;
        s += rev * x[(1 + n) * CDIM + c];
    }
    g_pp[blockIdx.x * CDIM + c] = s;
    if (c == 0) {
        float cc = 0.f;
        for (int i = 0; i < 64; i++) cc += (mask[n0 + i] < 0.5f) ? 1.f : 0.f;
        g_cntp[blockIdx.x] = cc;
    }
}

__global__ void back_finalize_kernel()
{
    const int c = threadIdx.x;             // 384 threads
    float cnt = 0.f;
    for (int b = 0; b < 64; b++) cnt += g_cntp[b];
    float s = 0.f;
    for (int b = 0; b < 64; b++) s += g_pp[b * CDIM + c];
    g_back[c] = s / (cnt + 1e-10f);
}

// ---------------- 2) kept-key compaction (1-block prefix scan) -------------
__global__ void scan_kernel(const float* __restrict__ mask,
                            const float* __restrict__ mask_block)
{
    __shared__ int sc[1024];
    const int t = threadIdx.x;
    const int base = t * 5;
    int flags[5];
    int cnt = 0;
#pragma unroll
    for (int e = 0; e < 5; e++) {
        int r = base + e;
        int f = 0;
        if (r < N_KV) {
            float mv = (r >= 1 && r <= N_Q - 2) ? mask[r - 1] : mask_block[r];
            f = (mv >= 0.5f) ? 1 : 0;
        }
        flags[e] = f;
        cnt += f;
    }
    sc[t] = cnt;
    if (t == 0) g_work = 0;                // reset attention work queue
    __syncthreads();
    for (int off = 1; off < 1024; off <<= 1) {
        int v = (t >= off) ? sc[t - off] : 0;
        __syncthreads();
        sc[t] += v;
        __syncthreads();
    }
    int o = sc[t] - cnt;
#pragma unroll
    for (int e = 0; e < 5; e++)
        if (flags[e]) g_idx[o++] = base + e;
    if (t == 1023) g_M = sc[1023];
}

// ---------------- 3) tf32 projection GEMM (R6-proven version) --------------
// mode 0: q = (x + pos[:N]) @ Wq^T * 1/8    -> g_q  (tf32-rounded)
// mode 1: k = (kv_x[idx] + pos[idx]) @ Wk^T -> g_k  (tf32-rounded, gathered)
// mode 2: v = kv_x[idx] @ Wv^T              -> g_v  (tf32-rounded, gathered)
// mode 3: o = g_o @ Wp^T + bp               -> d_out (fp32)
#define PROJ_SMEM (2 * (128 * 36 + 64 * 36) * (int)sizeof(unsigned))

__global__ __launch_bounds__(256)
void proj_tc(int base_mode,
             const float* __restrict__ x, const float* __restrict__ pos,
             const float* __restrict__ Wq_, const float* __restrict__ Wk_,
             const float* __restrict__ Wv_, const float* __restrict__ Wp_,
             const float* __restrict__ bias,
             float* __restrict__ out_param)
{
    extern __shared__ unsigned smP[];
    unsigned* smA = smP;                      // [2][128][36]
    unsigned* smW = smP + 2 * 128 * 36;       // [2][64][36]
#define AS(b, r, c) smA[(b) * (128 * 36) + (r) * 36 + (c)]
#define WS(b, r, c) smW[(b) * (64 * 36) + (r) * 36 + (c)]

    const int mode = base_mode + blockIdx.z;
    const int rows = (mode == 1 || mode == 2) ? g_M : N_Q;
    const int m0 = blockIdx.x * 128;
    if (m0 >= rows) return;
    const int j0 = blockIdx.y * 64;

    const float* W =
        (mode == 0) ? Wq_ : (mode == 1) ? Wk_ : (mode == 2) ? Wv_ : Wp_;
    float* outp = (mode == 0) ? g_q : (mode == 1) ? g_k : (mode == 2) ? g_v : out_param;

    const int tid  = threadIdx.x;
    const int warp = tid >> 5, lane = tid & 31;
    const int wm = warp >> 1, wn = warp & 1;
    const int g = lane >> 2, t = lane & 3;

    const float* pA[4];
    const float* pP[4];
    int rA[4];
#pragma unroll
    for (int i = 0; i < 4; i++) {
        const int lin = tid + i * 256;
        rA[i] = lin >> 3;
        const int mg = m0 + rA[i];
        pA[i] = nullptr; pP[i] = nullptr;
        if (mg < rows) {
            if (mode == 0) {
                pA[i] = x + mg * CDIM;
                pP[i] = pos + mg * CDIM;
            } else if (mode == 3) {
                pA[i] = g_o + mg * CDIM;
            } else {
                const int src = g_idx[mg];
                pA[i] = (src < N_Q) ? (x + src * CDIM) : g_back;
                if (mode == 1) pP[i] = pos + src * CDIM;
            }
        }
    }
    const float* pW[2];
    int rW[2];
#pragma unroll
    for (int i = 0; i < 2; i++) {
        const int lin = tid + i * 256;
        rW[i] = lin >> 3;
        pW[i] = W + (j0 + rW[i]) * CDIM;
    }
    const int cA = (tid & 7) * 4;

    float4 aReg[4], pReg[4], wReg[2];

#define PREFETCH(kt)                                                          \
    do {                                                                      \
        _Pragma("unroll")                                                     \
        for (int i = 0; i < 4; i++) {                                         \
            aReg[i] = pA[i] ? *(const float4*)(pA[i] + (kt) + cA)             \
                            : make_float4(0.f, 0.f, 0.f, 0.f);                \
            pReg[i] = pP[i] ? *(const float4*)(pP[i] + (kt) + cA)             \
                            : make_float4(0.f, 0.f, 0.f, 0.f);                \
        }                                                                     \
        _Pragma("unroll")                                                     \
        for (int i = 0; i < 2; i++)                                           \
            wReg[i] = *(const float4*)(pW[i] + (kt) + cA);                    \
    } while (0)

#define STORE(buf)                                                            \
    do {                                                                      \
        _Pragma("unroll")                                                     \
        for (int i = 0; i < 4; i++) {                                         \
            AS(buf, rA[i], cA + 0) = f2tf(aReg[i].x + pReg[i].x);             \
            AS(buf, rA[i], cA + 1) = f2tf(aReg[i].y + pReg[i].y);             \
            AS(buf, rA[i], cA + 2) = f2tf(aReg[i].z + pReg[i].z);             \
            AS(buf, rA[i], cA + 3) = f2tf(aReg[i].w + pReg[i].w);             \
        }                                                                     \
        _Pragma("unroll")                                                     \
        for (int i = 0; i < 2; i++) {                                         \
            WS(buf, rW[i], cA + 0) = f2tf(wReg[i].x);                         \
            WS(buf, rW[i], cA + 1) = f2tf(wReg[i].y);                         \
            WS(buf, rW[i], cA + 2) = f2tf(wReg[i].z);                         \
            WS(buf, rW[i], cA + 3) = f2tf(wReg[i].w);                         \
        }                                                                     \
    } while (0)

    float acc[2][4][4] = {};

    PREFETCH(0);
    STORE(0);
    __syncthreads();

    const int NT = CDIM / 32;              // 12
    for (int kt = 0; kt < NT; kt++) {
        const int cur = kt & 1;
        if (kt + 1 < NT) PREFETCH((kt + 1) * 32);

#pragma unroll
        for (int ks = 0; ks < 4; ks++) {
            unsigned a[2][4], b[4][2];
#pragma unroll
            for (int mt = 0; mt < 2; mt++) {
                const int rb = wm * 32 + mt * 16;
                a[mt][0] = AS(cur, rb + g,     ks * 8 + t    );
                a[mt][1] = AS(cur, rb + g + 8, ks * 8 + t    );
                a[mt][2] = AS(cur, rb + g,     ks * 8 + t + 4);
                a[mt][3] = AS(cur, rb + g + 8, ks * 8 + t + 4);
            }
#pragma unroll
            for (int nt = 0; nt < 4; nt++) {
                const int jb = wn * 32 + nt * 8;
                b[nt][0] = WS(cur, jb + g, ks * 8 + t    );
                b[nt][1] = WS(cur, jb + g, ks * 8 + t + 4);
            }
#pragma unroll
            for (int mt = 0; mt < 2; mt++)
#pragma unroll
                for (int nt = 0; nt < 4; nt++)
                    mma8(acc[mt][nt], a[mt], b[nt]);
        }

        if (kt + 1 < NT) STORE(cur ^ 1);
        __syncthreads();
    }

    const float oscale = (mode == 0) ? 0.125f : 1.0f;
#pragma unroll
    for (int mt = 0; mt < 2; mt++) {
#pragma unroll
        for (int nt = 0; nt < 4; nt++) {
            const int col = j0 + wn * 32 + nt * 8 + t * 2;
            const int r0 = m0 + wm * 32 + mt * 16 + g;
            const int r1 = r0 + 8;
            if (mode == 3) {
                const float b0 = bias ? bias[col]     : 0.f;
                const float b1 = bias ? bias[col + 1] : 0.f;
                if (r0 < rows)
                    *(float2*)&outp[r0 * CDIM + col] = make_float2(acc[mt][nt][0] + b0, acc[mt][nt][1] + b1);
                if (r1 < rows)
                    *(float2*)&outp[r1 * CDIM + col] = make_float2(acc[mt][nt][2] + b0, acc[mt][nt][3] + b1);
            } else {
                if (r0 < rows) {
                    float2 v = make_float2(
                        __uint_as_float(f2tf(acc[mt][nt][0] * oscale)),
                        __uint_as_float(f2tf(acc[mt][nt][1] * oscale)));
                    *(float2*)&outp[r0 * CDIM + col] = v;
                }
                if (r1 < rows) {
                    float2 v = make_float2(
                        __uint_as_float(f2tf(acc[mt][nt][2] * oscale)),
                        __uint_as_float(f2tf(acc[mt][nt][3] * oscale)));
                    *(float2*)&outp[r1 * CDIM + col] = v;
                }
            }
        }
    }
#undef AS
#undef WS
#undef PREFETCH
#undef STORE
}

// ---------------- 4) attention: work-stealing + plane-permuted cp.async ----
// 198 blocks x 256 threads; items pulled from g_work; item = (qtile, head)
// smem (words):
//   Q: 4 planes x 2048        @ 0       (plane = (row>>3 & 1) + 2*(dchunk&1))
//   K: 2 bufs x 2 planes x2048 @ 8192   (plane = d-half)
//   V: 2 bufs x 8 planes x 520 @ 16384  (plane = key&7, padded 512->520)
//   P: [128][68]              @ 24704
#define AK_OFF 8192
#define AV_OFF 16384
#define AP_OFF 24704
#define ATTN_SMEM ((AP_OFF + 128 * 68) * (int)sizeof(unsigned))

__global__ __launch_bounds__(256)
void attn_tc()
{
    extern __shared__ unsigned sm[];
    __shared__ int s_item;
    unsigned* Ps = sm + AP_OFF;

    const int M  = g_M;
    const int nT = (M + 63) >> 6;
    const int tid = threadIdx.x, warp = tid >> 5, lane = tid & 31;
    const int g = lane >> 2, t = lane & 3;
    const int rb = warp * 16;
    const unsigned smB = (unsigned)__cvta_generic_to_shared(sm);

    // ---- precompute staging dst addresses (constant across items) ----
    unsigned dstQ[8];
#pragma unroll
    for (int i = 0; i < 8; i++) {
        const int lin = tid + i * 256;
        const int qr = lin >> 4, c = lin & 15;
        dstQ[i] = smB + ((((qr >> 3) & 1) + 2 * (c & 1)) * 2048
                         + ((qr >> 4) * 8 + (c >> 1)) * 32 + (qr & 7) * 4) * 4u;
    }
    unsigned dstK[4], dstV[4];
#pragma unroll
    for (int i = 0; i < 4; i++) {
        const int lin = tid + i * 256;
        const int kr = lin >> 4, c = lin & 15;
        dstK[i] = ((c & 1) * 2048 + ((kr >> 3) * 8 + (c >> 1)) * 32 + (kr & 7) * 4) * 4u;
        dstV[i] = ((kr & 7) * 520 + (kr >> 3) * 64 + c * 4) * 4u;
    }
    const int laneV = t * 520 + g;         // per-lane V fold (words)
    const int pr0 = (rb + g) * 68;         // P row bases
    const int pr1 = (rb + g + 8) * 68;

#define STAGE_KV(kt, buf)                                                     \
    do {                                                                      \
        const unsigned kb = smB + (AK_OFF + (buf) * 4096) * 4u;               \
        const unsigned vb = smB + (AV_OFF + (buf) * 4160) * 4u;               \
        _Pragma("unroll")                                                     \
        for (int i = 0; i < 4; i++) {                                         \
            const int lin = tid + i * 256;                                    \
            const int kr = lin >> 4, c = lin & 15;                            \
            const int kg = (kt) * 64 + kr;                                    \
            const int sz = (kg < M) ? 16 : 0;                                 \
            cp16(kb + dstK[i], &g_k[kg * CDIM + h * HDIM + c * 4], sz);       \
            cp16(vb + dstV[i], &g_v[kg * CDIM + h * HDIM + c * 4], sz);       \
        }                                                                     \
    } while (0)

    for (;;) {
        __syncthreads();                   // smem reuse + s_item guard
        if (tid == 0) s_item = atomicAdd(&g_work, 1);
        __syncthreads();
        const int item = s_item;
        if (item >= NITEMS) break;
        const int h  = item % HEADS;
        const int q0 = (item / HEADS) * 128;

        // ---- stage Q (plane-permuted) ----
#pragma unroll
        for (int i = 0; i < 8; i++) {
            const int lin = tid + i * 256;
            const int qr = lin >> 4, c = lin & 15;
            cp16(dstQ[i], &g_q[(q0 + qr) * CDIM + h * HDIM + c * 4],
                 (q0 + qr < N_Q) ? 16 : 0);
        }
        STAGE_KV(0, 0);
        CP_COMMIT();                       // group: Q + tile0

        float m_lo = -1e30f, m_hi = -1e30f, l_lo = 0.f, l_hi = 0.f;
        float co[8][4] = {};

        for (int kt = 0; kt < nT; kt++) {
            const int cur = kt & 1;
            __syncthreads();
            if (kt + 1 < nT) {
                STAGE_KV(kt + 1, cur ^ 1);
                CP_COMMIT();
                CP_WAIT(1);
            } else {
                CP_WAIT(0);
            }
            __syncthreads();

            const unsigned* Ks = sm + AK_OFF + cur * 4096;
            const unsigned* Vs = sm + AV_OFF + cur * 4160;

            // ---- S = Q K^T (all offsets base+immediate) ----
            float cs[8][4] = {};
#pragma unroll
            for (int ks = 0; ks < 8; ks++) {
                unsigned a[4];
                const int qi = (warp * 8 + ks) * 32 + lane;
                a[0] = sm[qi];
                a[1] = sm[2048 + qi];
                a[2] = sm[4096 + qi];
                a[3] = sm[6144 + qi];
#pragma unroll
                for (int nt = 0; nt < 8; nt++) {
                    unsigned b[2];
                    const int ki = (nt * 8 + ks) * 32 + lane;
                    b[0] = Ks[ki];
                    b[1] = Ks[2048 + ki];
                    mma8(cs[nt], a, b);
                }
            }

            // ---- online softmax ----
            float tm_lo = -1e30f, tm_hi = -1e30f;
#pragma unroll
            for (int nt = 0; nt < 8; nt++) {
                const int c0 = kt * 64 + nt * 8 + t * 2;
                if (c0     >= M) { cs[nt][0] = -1e30f; cs[nt][2] = -1e30f; }
                if (c0 + 1 >= M) { cs[nt][1] = -1e30f; cs[nt][3] = -1e30f; }
                tm_lo = fmaxf(tm_lo, fmaxf(cs[nt][0], cs[nt][1]));
                tm_hi = fmaxf(tm_hi, fmaxf(cs[nt][2], cs[nt][3]));
            }
            tm_lo = fmaxf(tm_lo, __shfl_xor_sync(0xffffffffu, tm_lo, 1));
            tm_lo = fmaxf(tm_lo, __shfl_xor_sync(0xffffffffu, tm_lo, 2));
            tm_hi = fmaxf(tm_hi, __shfl_xor_sync(0xffffffffu, tm_hi, 1));
            tm_hi = fmaxf(tm_hi, __shfl_xor_sync(0xffffffffu, tm_hi, 2));

            const float mn_lo = fmaxf(m_lo, tm_lo);
            const float mn_hi = fmaxf(m_hi, tm_hi);
            const float corr_lo = __expf(m_lo - mn_lo);
            const float corr_hi = __expf(m_hi - mn_hi);
            m_lo = mn_lo; m_hi = mn_hi;

            float rs_lo = 0.f, rs_hi = 0.f;
#pragma unroll
            for (int nt = 0; nt < 8; nt++) {
                const float p0 = __expf(cs[nt][0] - mn_lo);
                const float p1 = __expf(cs[nt][1] - mn_lo);
                const float p2 = __expf(cs[nt][2] - mn_hi);
                const float p3 = __expf(cs[nt][3] - mn_hi);
                rs_lo += p0 + p1;
                rs_hi += p2 + p3;
                const int col = nt * 8 + t * 2;
                *(uint2*)&Ps[pr0 + col] = make_uint2(f2tf(p0), f2tf(p1));
                *(uint2*)&Ps[pr1 + col] = make_uint2(f2tf(p2), f2tf(p3));
            }
            rs_lo += __shfl_xor_sync(0xffffffffu, rs_lo, 1);
            rs_lo += __shfl_xor_sync(0xffffffffu, rs_lo, 2);
            rs_hi += __shfl_xor_sync(0xffffffffu, rs_hi, 1);
            rs_hi += __shfl_xor_sync(0xffffffffu, rs_hi, 2);
            l_lo = l_lo * corr_lo + rs_lo;
            l_hi = l_hi * corr_hi + rs_hi;

#pragma unroll
            for (int nt = 0; nt < 8; nt++) {
                co[nt][0] *= corr_lo; co[nt][1] *= corr_lo;
                co[nt][2] *= corr_hi; co[nt][3] *= corr_hi;
            }
            __syncwarp();    // order Ps stores (cross-lane) before A-frag loads

            // ---- O += P V (V planes: conflict-free, base+imm) ----
#pragma unroll
            for (int ks = 0; ks < 8; ks++) {
                unsigned a[4];
                a[0] = Ps[pr0 + ks * 8 + t    ];
                a[1] = Ps[pr1 + ks * 8 + t    ];
                a[2] = Ps[pr0 + ks * 8 + t + 4];
                a[3] = Ps[pr1 + ks * 8 + t + 4];
#pragma unroll
                for (int nt = 0; nt < 8; nt++) {
                    unsigned b[2];
                    const int vi = laneV + ks * 64 + nt * 8;
                    b[0] = Vs[vi];
                    b[1] = Vs[2080 + vi];      // +4 planes * 520
                    mma8(co[nt], a, b);
                }
            }
        }

        // ---- normalize + store (row-major g_o) ----
        const float inv_lo = 1.0f / l_lo;
        const float inv_hi = 1.0f / l_hi;
#pragma unroll
        for (int nt = 0; nt < 8; nt++) {
            const int d  = nt * 8 + t * 2;
            const int r0 = q0 + rb + g;
            const int r1 = r0 + 8;
            if (r0 < N_Q)
                *(float2*)&g_o[r0 * CDIM + h * HDIM + d] =
                    make_float2(co[nt][0] * inv_lo, co[nt][1] * inv_lo);
            if (r1 < N_Q)
                *(float2*)&g_o[r1 * CDIM + h * HDIM + d] =
                    make_float2(co[nt][2] * inv_hi, co[nt][3] * inv_hi);
        }
    }
#undef STAGE_KV
}

// ---------------- launch ---------------------------------------------------
extern "C" void kernel_launch(void* const* d_in, const int* in_sizes, int n_in,
                              void* d_out, int out_size)
{
    const float* x          = (const float*)d_in[0];
    const float* pos        = (const float*)d_in[1];
    const float* mask       = (const float*)d_in[2];
    const float* mask_block = (const float*)d_in[3];
    const float* Wq         = (const float*)d_in[4];
    const float* Wk         = (const float*)d_in[5];
    const float* Wv         = (const float*)d_in[6];
    const float* Wp         = (const float*)d_in[7];
    const float* bp         = (const float*)d_in[8];
    float* out = (float*)d_out;

    cudaFuncSetAttribute(attn_tc, cudaFuncAttributeMaxDynamicSharedMemorySize, ATTN_SMEM);
    cudaFuncSetAttribute(proj_tc, cudaFuncAttributeMaxDynamicSharedMemorySize, PROJ_SMEM);

    pool_kernel<<<64, CDIM>>>(x, mask);
    back_finalize_kernel<<<1, CDIM>>>();
    scan_kernel<<<1, 1024>>>(mask, mask_block);

    // fused Q/K/V projection: blockIdx.z = mode 0/1/2
    dim3 gqkv((N_Q + 127) / 128, CDIM / 64, 3);   // 33 x 6 x 3
    proj_tc<<<gqkv, 256, PROJ_SMEM>>>(0, x, pos, Wq, Wk, Wv, Wp, nullptr, nullptr);

    // work-stealing attention
    attn_tc<<<NITEMS, 256, ATTN_SMEM>>>();

    // output projection
    dim3 gout((N_Q + 127) / 128, CDIM / 64, 1);
    proj_tc<<<gout, 256, PROJ_SMEM>>>(3, x, pos, Wq, Wk, Wv, Wp, bp, out);
}

// round 10
// speedup vs baseline: 1.2181x; 1.2181x over previous
#include <cuda_runtime.h>
#include <cuda_bf16.h>
#include <math.h>

#define N_Q   4098
#define N_KV  4099
#define CDIM  384
#define HEADS 6
#define HDIM  64

// ---------------- scratch (device globals; allocation-free) ----------------
__device__ __align__(16) float g_pp[64 * CDIM];     // pooling partials
__device__ float  g_cntp[64];                       // count partials
__device__ __align__(16) float g_back[CDIM];        // back token
__device__ int    g_idx[N_KV];                      // kept key -> source row
__device__ int    g_M;                              // number of kept keys
__device__ __align__(16) float g_q[N_Q * CDIM];     // tf32-prerounded, prescaled 1/8
__device__ __align__(16) float g_k[N_KV * CDIM];    // tf32-prerounded
__device__ __align__(16) float g_v[N_KV * CDIM];    // tf32-prerounded
__device__ __align__(16) float g_o[N_Q * CDIM];

// ---------------- helpers ---------------------------------------------------
__device__ __forceinline__ unsigned f2tf(float x)
{
    unsigned r;
    asm("cvt.rna.tf32.f32 %0, %1;" : "=r"(r) : "f"(x));
    return r;
}

__device__ __forceinline__ void mma8(float* c, const unsigned* a, const unsigned* b)
{
    asm volatile(
        "mma.sync.aligned.m16n8k8.row.col.f32.tf32.tf32.f32 "
        "{%0,%1,%2,%3}, {%4,%5,%6,%7}, {%8,%9}, {%0,%1,%2,%3};\n"
        : "+f"(c[0]), "+f"(c[1]), "+f"(c[2]), "+f"(c[3])
        : "r"(a[0]), "r"(a[1]), "r"(a[2]), "r"(a[3]), "r"(b[0]), "r"(b[1]));
}

__device__ __forceinline__ void ldsm4(uint4& d, unsigned addr)
{
    asm volatile("ldmatrix.sync.aligned.m8n8.x4.shared.b16 {%0,%1,%2,%3}, [%4];"
                 : "=r"(d.x), "=r"(d.y), "=r"(d.z), "=r"(d.w) : "r"(addr));
}

__device__ __forceinline__ void cp16(unsigned dst, const void* src, int sz)
{
    asm volatile("cp.async.ca.shared.global [%0], [%1], 16, %2;"
                 :: "r"(dst), "l"(src), "r"(sz));
}
#define CP_COMMIT() asm volatile("cp.async.commit_group;")
#define CP_WAIT(n)  asm volatile("cp.async.wait_group %0;" :: "n"(n))

// ---------------- 1) background pooling (deterministic, 2-stage) -----------
__global__ void pool_kernel(const float* __restrict__ x, const float* __restrict__ mask)
{
    const int c  = threadIdx.x;            // 384 threads
    const int n0 = blockIdx.x * 64;
    float s = 0.f;
#pragma unroll 8
    for (int i = 0; i < 64; i++) {
        const int n = n0 + i;
        const float rev = (mask[n] < 0.5f) ? 1.f : 0.f;
        s += rev * x[(1 + n) * CDIM + c];
    }
    g_pp[blockIdx.x * CDIM + c] = s;
    if (c == 0) {
        float cc = 0.f;
        for (int i = 0; i < 64; i++) cc += (mask[n0 + i] < 0.5f) ? 1.f : 0.f;
        g_cntp[blockIdx.x] = cc;
    }
}

// ---------------- 2) scan + back-token finalize (fused) --------------------
__global__ void scan_kernel(const float* __restrict__ mask,
                            const float* __restrict__ mask_block)
{
    __shared__ int sc[1024];
    const int t = threadIdx.x;

    // back-token finalize (threads 0..383), independent of scan work
    if (t < CDIM) {
        float cnt = 0.f;
        for (int b = 0; b < 64; b++) cnt += g_cntp[b];
        float s = 0.f;
        for (int b = 0; b < 64; b++) s += g_pp[b * CDIM + t];
        g_back[t] = s / (cnt + 1e-10f);
    }

    const int base = t * 5;
    int flags[5];
    int cnt = 0;
#pragma unroll
    for (int e = 0; e < 5; e++) {
        int r = base + e;
        int f = 0;
        if (r < N_KV) {
            float mv = (r >= 1 && r <= N_Q - 2) ? mask[r - 1] : mask_block[r];
            f = (mv >= 0.5f) ? 1 : 0;
        }
        flags[e] = f;
        cnt += f;
    }
    sc[t] = cnt;
    __syncthreads();
    for (int off = 1; off < 1024; off <<= 1) {
        int v = (t >= off) ? sc[t - off] : 0;
        __syncthreads();
        sc[t] += v;
        __syncthreads();
    }
    int o = sc[t] - cnt;
#pragma unroll
    for (int e = 0; e < 5; e++)
        if (flags[e]) g_idx[o++] = base + e;
    if (t == 1023) g_M = sc[1023];
}

// ---------------- 3) tf32 projection GEMM (ldmatrix mainloop) --------------
// mode 0: q = (x + pos[:N]) @ Wq^T * 1/8    -> g_q  (tf32-rounded)
// mode 1: k = (kv_x[idx] + pos[idx]) @ Wk^T -> g_k  (tf32-rounded, gathered)
// mode 2: v = kv_x[idx] @ Wv^T              -> g_v  (tf32-rounded, gathered)
// mode 3: o = g_o @ Wp^T + bp               -> d_out (fp32)
// block tile 128(M) x 64(N), k-tile 32, 8 warps in 4(M) x 2(N)
#define PROJ_SMEM (2 * (128 * 36 + 64 * 36) * (int)sizeof(unsigned))

__global__ __launch_bounds__(256)
void proj_tc(int base_mode,
             const float* __restrict__ x, const float* __restrict__ pos,
             const float* __restrict__ Wq_, const float* __restrict__ Wk_,
             const float* __restrict__ Wv_, const float* __restrict__ Wp_,
             const float* __restrict__ bias,
             float* __restrict__ out_param)
{
    extern __shared__ unsigned smP[];
    unsigned* smA = smP;                      // [2][128][36]
    unsigned* smW = smP + 2 * 128 * 36;       // [2][64][36]
#define AS(b, r, c) smA[(b) * (128 * 36) + (r) * 36 + (c)]
#define WS(b, r, c) smW[(b) * (64 * 36) + (r) * 36 + (c)]

    const int mode = base_mode + blockIdx.z;
    const int rows = (mode == 1 || mode == 2) ? g_M : N_Q;
    const int m0 = blockIdx.x * 128;
    if (m0 >= rows) return;
    const int j0 = blockIdx.y * 64;

    const float* W =
        (mode == 0) ? Wq_ : (mode == 1) ? Wk_ : (mode == 2) ? Wv_ : Wp_;
    float* outp = (mode == 0) ? g_q : (mode == 1) ? g_k : (mode == 2) ? g_v : out_param;

    const int tid  = threadIdx.x;
    const int warp = tid >> 5, lane = tid & 31;
    const int wm = warp >> 1, wn = warp & 1;
    const int g = lane >> 2, t = lane & 3;
    const int m4 = lane >> 3, r8 = lane & 7;
    const unsigned smPB = (unsigned)__cvta_generic_to_shared(smP);

    // ldmatrix lane-base addresses (bytes)
    // A-frag: rows (wm*32 + mt*16) + 8*(m4&1) + r8, k-half = m4>>1
    const unsigned aA0 = smPB + ((wm * 32 + 8 * (m4 & 1) + r8) * 36) * 4u + (m4 >> 1) * 16u;
    // W B-frag: rows (wn*32 + ntp*16) + 8*(m4>>1) + r8, k-half = m4&1
    const unsigned aW0 = smPB + (2 * 128 * 36 + (wn * 32 + 8 * (m4 >> 1) + r8) * 36) * 4u
                       + (m4 & 1) * 16u;

    const float* pA[4];
    const float* pP[4];
    int rA[4];
#pragma unroll
    for (int i = 0; i < 4; i++) {
        const int lin = tid + i * 256;
        rA[i] = lin >> 3;
        const int mg = m0 + rA[i];
        pA[i] = nullptr; pP[i] = nullptr;
        if (mg < rows) {
            if (mode == 0) {
                pA[i] = x + mg * CDIM;
                pP[i] = pos + mg * CDIM;
            } else if (mode == 3) {
                pA[i] = g_o + mg * CDIM;
            } else {
                const int src = g_idx[mg];
                pA[i] = (src < N_Q) ? (x + src * CDIM) : g_back;
                if (mode == 1) pP[i] = pos + src * CDIM;
            }
        }
    }
    const float* pW[2];
    int rW[2];
#pragma unroll
    for (int i = 0; i < 2; i++) {
        const int lin = tid + i * 256;
        rW[i] = lin >> 3;
        pW[i] = W + (j0 + rW[i]) * CDIM;
    }
    const int cA = (tid & 7) * 4;

    float4 aReg[4], pReg[4], wReg[2];

#define PREFETCH(kt)                                                          \
    do {                                                                      \
        _Pragma("unroll")                                                     \
        for (int i = 0; i < 4; i++) {                                         \
            aReg[i] = pA[i] ? *(const float4*)(pA[i] + (kt) + cA)             \
                            : make_float4(0.f, 0.f, 0.f, 0.f);                \
            pReg[i] = pP[i] ? *(const float4*)(pP[i] + (kt) + cA)             \
                            : make_float4(0.f, 0.f, 0.f, 0.f);                \
        }                                                                     \
        _Pragma("unroll")                                                     \
        for (int i = 0; i < 2; i++)                                           \
            wReg[i] = *(const float4*)(pW[i] + (kt) + cA);                    \
    } while (0)

#define STORE(buf)                                                            \
    do {                                                                      \
        _Pragma("unroll")                                                     \
        for (int i = 0; i < 4; i++) {                                         \
            AS(buf, rA[i], cA + 0) = f2tf(aReg[i].x + pReg[i].x);             \
            AS(buf, rA[i], cA + 1) = f2tf(aReg[i].y + pReg[i].y);             \
            AS(buf, rA[i], cA + 2) = f2tf(aReg[i].z + pReg[i].z);             \
            AS(buf, rA[i], cA + 3) = f2tf(aReg[i].w + pReg[i].w);             \
        }                                                                     \
        _Pragma("unroll")                                                     \
        for (int i = 0; i < 2; i++) {                                         \
            WS(buf, rW[i], cA + 0) = f2tf(wReg[i].x);                         \
            WS(buf, rW[i], cA + 1) = f2tf(wReg[i].y);                         \
            WS(buf, rW[i], cA + 2) = f2tf(wReg[i].z);                         \
            WS(buf, rW[i], cA + 3) = f2tf(wReg[i].w);                         \
        }                                                                     \
    } while (0)

    float acc[2][4][4] = {};

    PREFETCH(0);
    STORE(0);
    __syncthreads();

    const int NT = CDIM / 32;              // 12
    for (int kt = 0; kt < NT; kt++) {
        const int cur = kt & 1;
        if (kt + 1 < NT) PREFETCH((kt + 1) * 32);

        const unsigned aAb = aA0 + cur * (128 * 36 * 4);   // +18432B per buffer
        const unsigned aWb = aW0 + cur * (64 * 36 * 4);    // +9216B per buffer
#pragma unroll
        for (int ks = 0; ks < 4; ks++) {
            uint4 av[2], bv[2];
#pragma unroll
            for (int mt = 0; mt < 2; mt++)
                ldsm4(av[mt], aAb + mt * (16 * 36 * 4) + ks * 32);
#pragma unroll
            for (int np = 0; np < 2; np++)
                ldsm4(bv[np], aWb + np * (16 * 36 * 4) + ks * 32);
#pragma unroll
            for (int mt = 0; mt < 2; mt++)
#pragma unroll
                for (int np = 0; np < 2; np++) {
                    mma8(acc[mt][2 * np    ], (const unsigned*)&av[mt], (const unsigned*)&bv[np].x);
                    mma8(acc[mt][2 * np + 1], (const unsigned*)&av[mt], (const unsigned*)&bv[np].z);
                }
        }

        if (kt + 1 < NT) STORE(cur ^ 1);
        __syncthreads();
    }

    const float oscale = (mode == 0) ? 0.125f : 1.0f;
#pragma unroll
    for (int mt = 0; mt < 2; mt++) {
#pragma unroll
        for (int nt = 0; nt < 4; nt++) {
            const int col = j0 + wn * 32 + nt * 8 + t * 2;
            const int r0 = m0 + wm * 32 + mt * 16 + g;
            const int r1 = r0 + 8;
            if (mode == 3) {
                const float b0 = bias ? bias[col]     : 0.f;
                const float b1 = bias ? bias[col + 1] : 0.f;
                if (r0 < rows)
                    *(float2*)&outp[r0 * CDIM + col] = make_float2(acc[mt][nt][0] + b0, acc[mt][nt][1] + b1);
                if (r1 < rows)
                    *(float2*)&outp[r1 * CDIM + col] = make_float2(acc[mt][nt][2] + b0, acc[mt][nt][3] + b1);
            } else {
                if (r0 < rows) {
                    float2 v = make_float2(
                        __uint_as_float(f2tf(acc[mt][nt][0] * oscale)),
                        __uint_as_float(f2tf(acc[mt][nt][1] * oscale)));
                    *(float2*)&outp[r0 * CDIM + col] = v;
                }
                if (r1 < rows) {
                    float2 v = make_float2(
                        __uint_as_float(f2tf(acc[mt][nt][2] * oscale)),
                        __uint_as_float(f2tf(acc[mt][nt][3] * oscale)));
                    *(float2*)&outp[r1 * CDIM + col] = v;
                }
            }
        }
    }
#undef AS
#undef WS
#undef PREFETCH
#undef STORE
}

// ---------------- 4) tf32 flash attention (R6 layout + ldmatrix) -----------
// grid (33, HEADS), block 256 (8 warps x 16 q-rows each)
// smem (words): Q[128][68] | K[2][64][68] | V[2][64][72] | P[128][68]
#define AT_STRIDE 68
#define V_STRIDE  72
#define K_OFF (128 * AT_STRIDE)
#define V_OFF (K_OFF + 2 * 64 * AT_STRIDE)
#define P_OFF (V_OFF + 2 * 64 * V_STRIDE)
#define ATTN_SMEM ((P_OFF + 128 * AT_STRIDE) * (int)sizeof(unsigned))

__global__ __launch_bounds__(256)
void attn_tc()
{
    extern __shared__ unsigned sm[];
    unsigned* Ps = sm + P_OFF;

    const int h  = blockIdx.y;
    const int q0 = blockIdx.x * 128;
    const int M  = g_M;
    const int tid = threadIdx.x, warp = tid >> 5, lane = tid & 31;
    const int g = lane >> 2, t = lane & 3;
    const int rb = warp * 16;
    const int m4 = lane >> 3, r8 = lane & 7;
    const unsigned smB = (unsigned)__cvta_generic_to_shared(sm);

    // ldmatrix lane-base addresses (bytes)
    const unsigned aQ = smB + ((rb + 8 * (m4 & 1) + r8) * AT_STRIDE) * 4u + (m4 >> 1) * 16u;
    const unsigned aP = smB + (P_OFF + (rb + 8 * (m4 & 1) + r8) * AT_STRIDE) * 4u + (m4 >> 1) * 16u;
    const unsigned aKc = ((8 * (m4 >> 1) + r8) * AT_STRIDE) * 4u + (m4 & 1) * 16u;

    // ---- async stage Q tile [128 q][64 d] (pre-rounded + pre-scaled) ----
#pragma unroll
    for (int i = 0; i < 8; i++) {
        const int lin = tid + i * 256;
        const int r = lin >> 4, c4 = (lin & 15) * 4;
        cp16(smB + (r * AT_STRIDE + c4) * 4u,
             &g_q[(q0 + r) * CDIM + h * HDIM + c4],
             (q0 + r < N_Q) ? 16 : 0);
    }

#define STAGE_KV(kt, buf)                                                     \
    do {                                                                      \
        _Pragma("unroll")                                                     \
        for (int i = 0; i < 4; i++) {                                         \
            const int lin = tid + i * 256;                                    \
            const int r = lin >> 4, c4 = (lin & 15) * 4;                      \
            const int kg = (kt) * 64 + r;                                     \
            const int sz = (kg < M) ? 16 : 0;                                 \
            cp16(smB + ((K_OFF + (buf) * 64 * AT_STRIDE) + r * AT_STRIDE + c4) * 4u, \
                 &g_k[kg * CDIM + h * HDIM + c4], sz);                        \
            cp16(smB + ((V_OFF + (buf) * 64 * V_STRIDE) + r * V_STRIDE + c4) * 4u,   \
                 &g_v[kg * CDIM + h * HDIM + c4], sz);                        \
        }                                                                     \
    } while (0)

    const int nT = (M + 63) >> 6;
    STAGE_KV(0, 0);
    CP_COMMIT();                           // group: Q + tile0

    float m_lo = -1e30f, m_hi = -1e30f, l_lo = 0.f, l_hi = 0.f;
    float co[8][4] = {};

    for (int kt = 0; kt < nT; kt++) {
        const int cur = kt & 1;
        __syncthreads();                   // all warps done with buffer cur^1
        if (kt + 1 < nT) {
            STAGE_KV(kt + 1, cur ^ 1);
            CP_COMMIT();
            CP_WAIT(1);
        } else {
            CP_WAIT(0);
        }
        __syncthreads();

        const unsigned kBase = smB + (K_OFF + cur * 64 * AT_STRIDE) * 4u + aKc;
        const unsigned* Vs = sm + V_OFF + cur * 64 * V_STRIDE;

        // ---- S = Q K^T via ldmatrix ----
        float cs[8][4] = {};
#pragma unroll
        for (int ks = 0; ks < 8; ks++) {
            uint4 a;
            ldsm4(a, aQ + ks * 32);
#pragma unroll
            for (int j = 0; j < 4; j++) {
                uint4 b;
                ldsm4(b, kBase + j * (16 * AT_STRIDE * 4) + ks * 32);
                mma8(cs[2 * j    ], (const unsigned*)&a, (const unsigned*)&b.x);
                mma8(cs[2 * j + 1], (const unsigned*)&a, (const unsigned*)&b.z);
            }
        }

        // ---- online softmax ----
        if (kt == nT - 1) {                // tail tile: mask invalid keys
#pragma unroll
            for (int nt = 0; nt < 8; nt++) {
                const int c0 = kt * 64 + nt * 8 + t * 2;
                if (c0     >= M) { cs[nt][0] = -1e30f; cs[nt][2] = -1e30f; }
                if (c0 + 1 >= M) { cs[nt][1] = -1e30f; cs[nt][3] = -1e30f; }
            }
        }
        float tm_lo = -1e30f, tm_hi = -1e30f;
#pragma unroll
        for (int nt = 0; nt < 8; nt++) {
            tm_lo = fmaxf(tm_lo, fmaxf(cs[nt][0], cs[nt][1]));
            tm_hi = fmaxf(tm_hi, fmaxf(cs[nt][2], cs[nt][3]));
        }
        tm_lo = fmaxf(tm_lo, __shfl_xor_sync(0xffffffffu, tm_lo, 1));
        tm_lo = fmaxf(tm_lo, __shfl_xor_sync(0xffffffffu, tm_lo, 2));
        tm_hi = fmaxf(tm_hi, __shfl_xor_sync(0xffffffffu, tm_hi, 1));
        tm_hi = fmaxf(tm_hi, __shfl_xor_sync(0xffffffffu, tm_hi, 2));

        const float mn_lo = fmaxf(m_lo, tm_lo);
        const float mn_hi = fmaxf(m_hi, tm_hi);
        const float corr_lo = __expf(m_lo - mn_lo);
        const float corr_hi = __expf(m_hi - mn_hi);
        m_lo = mn_lo; m_hi = mn_hi;

        float rs_lo = 0.f, rs_hi = 0.f;
#pragma unroll
        for (int nt = 0; nt < 8; nt++) {
            const float p0 = __expf(cs[nt][0] - mn_lo);
            const float p1 = __expf(cs[nt][1] - mn_lo);
            const float p2 = __expf(cs[nt][2] - mn_hi);
            const float p3 = __expf(cs[nt][3] - mn_hi);
            rs_lo += p0 + p1;
            rs_hi += p2 + p3;
            const int col = nt * 8 + t * 2;
            *(uint2*)&Ps[(rb + g    ) * AT_STRIDE + col] = make_uint2(f2tf(p0), f2tf(p1));
            *(uint2*)&Ps[(rb + g + 8) * AT_STRIDE + col] = make_uint2(f2tf(p2), f2tf(p3));
        }
        rs_lo += __shfl_xor_sync(0xffffffffu, rs_lo, 1);
        rs_lo += __shfl_xor_sync(0xffffffffu, rs_lo, 2);
        rs_hi += __shfl_xor_sync(0xffffffffu, rs_hi, 1);
        rs_hi += __shfl_xor_sync(0xffffffffu, rs_hi, 2);
        l_lo = l_lo * corr_lo + rs_lo;
        l_hi = l_hi * corr_hi + rs_hi;

#pragma unroll
        for (int nt = 0; nt < 8; nt++) {
            co[nt][0] *= corr_lo; co[nt][1] *= corr_lo;
            co[nt][2] *= corr_hi; co[nt][3] *= corr_hi;
        }
        __syncwarp();    // order Ps stores (cross-lane) before ldmatrix loads

        // ---- O += P V (P via ldmatrix, V via LDS stride-72) ----
#pragma unroll
        for (int ks = 0; ks < 8; ks++) {
            uint4 a;
            ldsm4(a, aP + ks * 32);
#pragma unroll
            for (int nt = 0; nt < 8; nt++) {
                unsigned b[2];
                b[0] = Vs[(ks * 8 + t    ) * V_STRIDE + nt * 8 + g];
                b[1] = Vs[(ks * 8 + t + 4) * V_STRIDE + nt * 8 + g];
                mma8(co[nt], (const unsigned*)&a, b);
            }
        }
    }

    // ---- normalize + store (row-major g_o) ----
    const float inv_lo = 1.0f / l_lo;
    const float inv_hi = 1.0f / l_hi;
#pragma unroll
    for (int nt = 0; nt < 8; nt++) {
        const int d  = nt * 8 + t * 2;
        const int r0 = q0 + rb + g;
        const int r1 = r0 + 8;
        if (r0 < N_Q)
            *(float2*)&g_o[r0 * CDIM + h * HDIM + d] =
                make_float2(co[nt][0] * inv_lo, co[nt][1] * inv_lo);
        if (r1 < N_Q)
            *(float2*)&g_o[r1 * CDIM + h * HDIM + d] =
                make_float2(co[nt][2] * inv_hi, co[nt][3] * inv_hi);
    }
#undef STAGE_KV
}

// ---------------- launch ---------------------------------------------------
extern "C" void kernel_launch(void* const* d_in, const int* in_sizes, int n_in,
                              void* d_out, int out_size)
{
    const float* x          = (const float*)d_in[0];
    const float* pos        = (const float*)d_in[1];
    const float* mask       = (const float*)d_in[2];
    const float* mask_block = (const float*)d_in[3];
    const float* Wq         = (const float*)d_in[4];
    const float* Wk         = (const float*)d_in[5];
    const float* Wv         = (const float*)d_in[6];
    const float* Wp         = (const float*)d_in[7];
    const float* bp         = (const float*)d_in[8];
    float* out = (float*)d_out;

    cudaFuncSetAttribute(attn_tc, cudaFuncAttributeMaxDynamicSharedMemorySize, ATTN_SMEM);
    cudaFuncSetAttribute(proj_tc, cudaFuncAttributeMaxDynamicSharedMemorySize, PROJ_SMEM);

    pool_kernel<<<64, CDIM>>>(x, mask);
    scan_kernel<<<1, 1024>>>(mask, mask_block);   // also finalizes back token

    // fused Q/K/V projection: blockIdx.z = mode 0/1/2
    dim3 gqkv((N_Q + 127) / 128, CDIM / 64, 3);   // 33 x 6 x 3
    proj_tc<<<gqkv, 256, PROJ_SMEM>>>(0, x, pos, Wq, Wk, Wv, Wp, nullptr, nullptr);

    dim3 gattn((N_Q + 127) / 128, HEADS);         // 33 x 6
    attn_tc<<<gattn, 256, ATTN_SMEM>>>();

    // output projection
    dim3 gout((N_Q + 127) / 128, CDIM / 64, 1);
    proj_tc<<<gout, 256, PROJ_SMEM>>>(3, x, pos, Wq, Wk, Wv, Wp, bp, out);
}

// round 11
// speedup vs baseline: 1.3053x; 1.0715x over previous
#include <cuda_runtime.h>
#include <cuda_bf16.h>
#include <math.h>

#define N_Q   4098
#define N_KV  4099
#define CDIM  384
#define HEADS 6
#define HDIM  64

// ---------------- scratch (device globals; allocation-free) ----------------
__device__ __align__(16) float g_pp[64 * CDIM];     // pooling partials
__device__ float  g_cntp[64];                       // count partials
__device__ __align__(16) float g_back[CDIM];        // back token
__device__ int    g_idx[N_KV];                      // kept key -> source row
__device__ int    g_M;                              // number of kept keys
__device__ __align__(16) float g_q[N_Q * CDIM];     // tf32-prerounded, prescaled 1/8
__device__ __align__(16) float g_k[N_KV * CDIM];    // tf32-prerounded
__device__ __align__(16) float g_v[N_KV * CDIM];    // tf32-prerounded
__device__ __align__(16) float g_o[N_Q * CDIM];

// ---------------- helpers ---------------------------------------------------
__device__ __forceinline__ unsigned f2tf(float x)
{
    unsigned r;
    asm("cvt.rna.tf32.f32 %0, %1;" : "=r"(r) : "f"(x));
    return r;
}

__device__ __forceinline__ void mma8(float* c, const unsigned* a, const unsigned* b)
{
    asm volatile(
        "mma.sync.aligned.m16n8k8.row.col.f32.tf32.tf32.f32 "
        "{%0,%1,%2,%3}, {%4,%5,%6,%7}, {%8,%9}, {%0,%1,%2,%3};\n"
        : "+f"(c[0]), "+f"(c[1]), "+f"(c[2]), "+f"(c[3])
        : "r"(a[0]), "r"(a[1]), "r"(a[2]), "r"(a[3]), "r"(b[0]), "r"(b[1]));
}

__device__ __forceinline__ void ldsm4(uint4& d, unsigned addr)
{
    asm volatile("ldmatrix.sync.aligned.m8n8.x4.shared.b16 {%0,%1,%2,%3}, [%4];"
                 : "=r"(d.x), "=r"(d.y), "=r"(d.z), "=r"(d.w) : "r"(addr));
}

__device__ __forceinline__ void cp16(unsigned dst, const void* src, int sz)
{
    asm volatile("cp.async.ca.shared.global [%0], [%1], 16, %2;"
                 :: "r"(dst), "l"(src), "r"(sz));
}
#define CP_COMMIT() asm volatile("cp.async.commit_group;")
#define CP_WAIT(n)  asm volatile("cp.async.wait_group %0;" :: "n"(n))

// ---------------- 1) background pooling (deterministic, 2-stage) -----------
__global__ void pool_kernel(const float* __restrict__ x, const float* __restrict__ mask)
{
    const int c  = threadIdx.x;            // 384 threads
    const int n0 = blockIdx.x * 64;
    float s = 0.f;
#pragma unroll 8
    for (int i = 0; i < 64; i++) {
        const int n = n0 + i;
        const float rev = (mask[n] < 0.5f) ? 1.f : 0.f;
        s += rev * x[(1 + n) * CDIM + c];
    }
    g_pp[blockIdx.x * CDIM + c] = s;
    if (c == 0) {
        float cc = 0.f;
        for (int i = 0; i < 64; i++) cc += (mask[n0 + i] < 0.5f) ? 1.f : 0.f;
        g_cntp[blockIdx.x] = cc;
    }
}

// ---------------- 2) scan + back-token finalize (fused) --------------------
__global__ void scan_kernel(const float* __restrict__ mask,
                            const float* __restrict__ mask_block)
{
    __shared__ int sc[1024];
    const int t = threadIdx.x;

    // back-token finalize (threads 0..383), independent of scan work
    if (t < CDIM) {
        float cnt = 0.f;
        for (int b = 0; b < 64; b++) cnt += g_cntp[b];
        float s = 0.f;
        for (int b = 0; b < 64; b++) s += g_pp[b * CDIM + t];
        g_back[t] = s / (cnt + 1e-10f);
    }

    const int base = t * 5;
    int flags[5];
    int cnt = 0;
#pragma unroll
    for (int e = 0; e < 5; e++) {
        int r = base + e;
        int f = 0;
        if (r < N_KV) {
            float mv = (r >= 1 && r <= N_Q - 2) ? mask[r - 1] : mask_block[r];
            f = (mv >= 0.5f) ? 1 : 0;
        }
        flags[e] = f;
        cnt += f;
    }
    sc[t] = cnt;
    __syncthreads();
    for (int off = 1; off < 1024; off <<= 1) {
        int v = (t >= off) ? sc[t - off] : 0;
        __syncthreads();
        sc[t] += v;
        __syncthreads();
    }
    int o = sc[t] - cnt;
#pragma unroll
    for (int e = 0; e < 5; e++)
        if (flags[e]) g_idx[o++] = base + e;
    if (t == 1023) g_M = sc[1023];
}

// ---------------- 3) tf32 projection GEMM (ldmatrix mainloop) --------------
// mode 0: q = (x + pos[:N]) @ Wq^T * 1/8    -> g_q  (tf32-rounded)
// mode 1: k = (kv_x[idx] + pos[idx]) @ Wk^T -> g_k  (tf32-rounded, gathered)
// mode 2: v = kv_x[idx] @ Wv^T              -> g_v  (tf32-rounded, gathered)
// mode 3: o = g_o @ Wp^T + bp               -> d_out (fp32)
// block tile 128(M) x 64(N), k-tile 32, 8 warps in 4(M) x 2(N)
#define PROJ_SMEM (2 * (128 * 36 + 64 * 36) * (int)sizeof(unsigned))

__global__ __launch_bounds__(256)
void proj_tc(int base_mode,
             const float* __restrict__ x, const float* __restrict__ pos,
             const float* __restrict__ Wq_, const float* __restrict__ Wk_,
             const float* __restrict__ Wv_, const float* __restrict__ Wp_,
             const float* __restrict__ bias,
             float* __restrict__ out_param)
{
    extern __shared__ unsigned smP[];
    unsigned* smA = smP;                      // [2][128][36]
    unsigned* smW = smP + 2 * 128 * 36;       // [2][64][36]
#define AS(b, r, c) smA[(b) * (128 * 36) + (r) * 36 + (c)]
#define WS(b, r, c) smW[(b) * (64 * 36) + (r) * 36 + (c)]

    const int mode = base_mode + blockIdx.z;
    const int rows = (mode == 1 || mode == 2) ? g_M : N_Q;
    const int m0 = blockIdx.x * 128;
    if (m0 >= rows) return;
    const int j0 = blockIdx.y * 64;

    const float* W =
        (mode == 0) ? Wq_ : (mode == 1) ? Wk_ : (mode == 2) ? Wv_ : Wp_;
    float* outp = (mode == 0) ? g_q : (mode == 1) ? g_k : (mode == 2) ? g_v : out_param;

    const int tid  = threadIdx.x;
    const int warp = tid >> 5, lane = tid & 31;
    const int wm = warp >> 1, wn = warp & 1;
    const int g = lane >> 2, t = lane & 3;
    const int m4 = lane >> 3, r8 = lane & 7;
    const unsigned smPB = (unsigned)__cvta_generic_to_shared(smP);

    const unsigned aA0 = smPB + ((wm * 32 + 8 * (m4 & 1) + r8) * 36) * 4u + (m4 >> 1) * 16u;
    const unsigned aW0 = smPB + (2 * 128 * 36 + (wn * 32 + 8 * (m4 >> 1) + r8) * 36) * 4u
                       + (m4 & 1) * 16u;

    const float* pA[4];
    const float* pP[4];
    int rA[4];
#pragma unroll
    for (int i = 0; i < 4; i++) {
        const int lin = tid + i * 256;
        rA[i] = lin >> 3;
        const int mg = m0 + rA[i];
        pA[i] = nullptr; pP[i] = nullptr;
        if (mg < rows) {
            if (mode == 0) {
                pA[i] = x + mg * CDIM;
                pP[i] = pos + mg * CDIM;
            } else if (mode == 3) {
                pA[i] = g_o + mg * CDIM;
            } else {
                const int src = g_idx[mg];
                pA[i] = (src < N_Q) ? (x + src * CDIM) : g_back;
                if (mode == 1) pP[i] = pos + src * CDIM;
            }
        }
    }
    const float* pW[2];
    int rW[2];
#pragma unroll
    for (int i = 0; i < 2; i++) {
        const int lin = tid + i * 256;
        rW[i] = lin >> 3;
        pW[i] = W + (j0 + rW[i]) * CDIM;
    }
    const int cA = (tid & 7) * 4;

    float4 aReg[4], pReg[4], wReg[2];

#define PREFETCH(kt)                                                          \
    do {                                                                      \
        _Pragma("unroll")                                                     \
        for (int i = 0; i < 4; i++) {                                         \
            aReg[i] = pA[i] ? *(const float4*)(pA[i] + (kt) + cA)             \
                            : make_float4(0.f, 0.f, 0.f, 0.f);                \
            pReg[i] = pP[i] ? *(const float4*)(pP[i] + (kt) + cA)             \
                            : make_float4(0.f, 0.f, 0.f, 0.f);                \
        }                                                                     \
        _Pragma("unroll")                                                     \
        for (int i = 0; i < 2; i++)                                           \
            wReg[i] = *(const float4*)(pW[i] + (kt) + cA);                    \
    } while (0)

#define STORE(buf)                                                            \
    do {                                                                      \
        _Pragma("unroll")                                                     \
        for (int i = 0; i < 4; i++) {                                         \
            AS(buf, rA[i], cA + 0) = f2tf(aReg[i].x + pReg[i].x);             \
            AS(buf, rA[i], cA + 1) = f2tf(aReg[i].y + pReg[i].y);             \
            AS(buf, rA[i], cA + 2) = f2tf(aReg[i].z + pReg[i].z);             \
            AS(buf, rA[i], cA + 3) = f2tf(aReg[i].w + pReg[i].w);             \
        }                                                                     \
        _Pragma("unroll")                                                     \
        for (int i = 0; i < 2; i++) {                                         \
            WS(buf, rW[i], cA + 0) = f2tf(wReg[i].x);                         \
            WS(buf, rW[i], cA + 1) = f2tf(wReg[i].y);                         \
            WS(buf, rW[i], cA + 2) = f2tf(wReg[i].z);                         \
            WS(buf, rW[i], cA + 3) = f2tf(wReg[i].w);                         \
        }                                                                     \
    } while (0)

    float acc[2][4][4] = {};

    PREFETCH(0);
    STORE(0);
    __syncthreads();

    const int NT = CDIM / 32;              // 12
    for (int kt = 0; kt < NT; kt++) {
        const int cur = kt & 1;
        if (kt + 1 < NT) PREFETCH((kt + 1) * 32);

        const unsigned aAb = aA0 + cur * (128 * 36 * 4);
        const unsigned aWb = aW0 + cur * (64 * 36 * 4);
#pragma unroll
        for (int ks = 0; ks < 4; ks++) {
            uint4 av[2], bv[2];
#pragma unroll
            for (int mt = 0; mt < 2; mt++)
                ldsm4(av[mt], aAb + mt * (16 * 36 * 4) + ks * 32);
#pragma unroll
            for (int np = 0; np < 2; np++)
                ldsm4(bv[np], aWb + np * (16 * 36 * 4) + ks * 32);
#pragma unroll
            for (int mt = 0; mt < 2; mt++)
#pragma unroll
                for (int np = 0; np < 2; np++) {
                    mma8(acc[mt][2 * np    ], (const unsigned*)&av[mt], (const unsigned*)&bv[np].x);
                    mma8(acc[mt][2 * np + 1], (const unsigned*)&av[mt], (const unsigned*)&bv[np].z);
                }
        }

        if (kt + 1 < NT) STORE(cur ^ 1);
        __syncthreads();
    }

    const float oscale = (mode == 0) ? 0.125f : 1.0f;
#pragma unroll
    for (int mt = 0; mt < 2; mt++) {
#pragma unroll
        for (int nt = 0; nt < 4; nt++) {
            const int col = j0 + wn * 32 + nt * 8 + t * 2;
            const int r0 = m0 + wm * 32 + mt * 16 + g;
            const int r1 = r0 + 8;
            if (mode == 3) {
                const float b0 = bias ? bias[col]     : 0.f;
                const float b1 = bias ? bias[col + 1] : 0.f;
                if (r0 < rows)
                    *(float2*)&outp[r0 * CDIM + col] = make_float2(acc[mt][nt][0] + b0, acc[mt][nt][1] + b1);
                if (r1 < rows)
                    *(float2*)&outp[r1 * CDIM + col] = make_float2(acc[mt][nt][2] + b0, acc[mt][nt][3] + b1);
            } else {
                if (r0 < rows) {
                    float2 v = make_float2(
                        __uint_as_float(f2tf(acc[mt][nt][0] * oscale)),
                        __uint_as_float(f2tf(acc[mt][nt][1] * oscale)));
                    *(float2*)&outp[r0 * CDIM + col] = v;
                }
                if (r1 < rows) {
                    float2 v = make_float2(
                        __uint_as_float(f2tf(acc[mt][nt][2] * oscale)),
                        __uint_as_float(f2tf(acc[mt][nt][3] * oscale)));
                    *(float2*)&outp[r1 * CDIM + col] = v;
                }
            }
        }
    }
#undef AS
#undef WS
#undef PREFETCH
#undef STORE
}

// ---------------- 4) tf32 flash attention (no P smem; quad-shuffle PV) -----
// grid (33, HEADS), block 256 (8 warps x 16 q-rows each), 2 CTAs/SM
// smem (words): Q[128][68] | K[2][64][68] | V[2][64][72]   = 104 KB
#define AT_STRIDE 68
#define V_STRIDE  72
#define K_OFF (128 * AT_STRIDE)
#define V_OFF (K_OFF + 2 * 64 * AT_STRIDE)
#define ATTN_SMEM ((V_OFF + 2 * 64 * V_STRIDE) * (int)sizeof(unsigned))

__global__ __launch_bounds__(256, 2)
void attn_tc()
{
    extern __shared__ unsigned sm[];

    const int h  = blockIdx.y;
    const int q0 = blockIdx.x * 128;
    const int M  = g_M;
    const int tid = threadIdx.x, warp = tid >> 5, lane = tid & 31;
    const int g = lane >> 2, t = lane & 3;
    const int rb = warp * 16;
    const int m4 = lane >> 3, r8 = lane & 7;
    const unsigned smB = (unsigned)__cvta_generic_to_shared(sm);

    // ldmatrix lane-base addresses (bytes)
    const unsigned aQ  = smB + ((rb + 8 * (m4 & 1) + r8) * AT_STRIDE) * 4u + (m4 >> 1) * 16u;
    const unsigned aKc = ((8 * (m4 >> 1) + r8) * AT_STRIDE) * 4u + (m4 & 1) * 16u;
    // quad-shuffle source lanes for PV A-frag rebuild
    const int src0 = (lane & 28) | (t >> 1);
    const int src1 = src0 + 2;
    const bool oddt = (t & 1);

    // ---- async stage Q tile [128 q][64 d] (pre-rounded + pre-scaled) ----
#pragma unroll
    for (int i = 0; i < 8; i++) {
        const int lin = tid + i * 256;
        const int r = lin >> 4, c4 = (lin & 15) * 4;
        cp16(smB + (r * AT_STRIDE + c4) * 4u,
             &g_q[(q0 + r) * CDIM + h * HDIM + c4],
             (q0 + r < N_Q) ? 16 : 0);
    }

#define STAGE_KV(kt, buf)                                                     \
    do {                                                                      \
        _Pragma("unroll")                                                     \
        for (int i = 0; i < 4; i++) {                                         \
            const int lin = tid + i * 256;                                    \
            const int r = lin >> 4, c4 = (lin & 15) * 4;                      \
            const int kg = (kt) * 64 + r;                                     \
            const int sz = (kg < M) ? 16 : 0;                                 \
            cp16(smB + ((K_OFF + (buf) * 64 * AT_STRIDE) + r * AT_STRIDE + c4) * 4u, \
                 &g_k[kg * CDIM + h * HDIM + c4], sz);                        \
            cp16(smB + ((V_OFF + (buf) * 64 * V_STRIDE) + r * V_STRIDE + c4) * 4u,   \
                 &g_v[kg * CDIM + h * HDIM + c4], sz);                        \
        }                                                                     \
    } while (0)

    const int nT = (M + 63) >> 6;
    STAGE_KV(0, 0);
    CP_COMMIT();                           // group: Q + tile0

    float m_lo = -1e30f, m_hi = -1e30f, l_lo = 0.f, l_hi = 0.f;
    float co[8][4] = {};

    for (int kt = 0; kt < nT; kt++) {
        const int cur = kt & 1;
        __syncthreads();                   // all warps done with buffer cur^1
        if (kt + 1 < nT) {
            STAGE_KV(kt + 1, cur ^ 1);
            CP_COMMIT();
            CP_WAIT(1);
        } else {
            CP_WAIT(0);
        }
        __syncthreads();

        const unsigned kBase = smB + (K_OFF + cur * 64 * AT_STRIDE) * 4u + aKc;
        const unsigned* Vs = sm + V_OFF + cur * 64 * V_STRIDE;

        // ---- S = Q K^T via ldmatrix ----
        float cs[8][4] = {};
#pragma unroll
        for (int ks = 0; ks < 8; ks++) {
            uint4 a;
            ldsm4(a, aQ + ks * 32);
#pragma unroll
            for (int j = 0; j < 4; j++) {
                uint4 b;
                ldsm4(b, kBase + j * (16 * AT_STRIDE * 4) + ks * 32);
                mma8(cs[2 * j    ], (const unsigned*)&a, (const unsigned*)&b.x);
                mma8(cs[2 * j + 1], (const unsigned*)&a, (const unsigned*)&b.z);
            }
        }

        // ---- online softmax ----
        if (kt == nT - 1) {                // tail tile: mask invalid keys
#pragma unroll
            for (int nt = 0; nt < 8; nt++) {
                const int c0 = kt * 64 + nt * 8 + t * 2;
                if (c0     >= M) { cs[nt][0] = -1e30f; cs[nt][2] = -1e30f; }
                if (c0 + 1 >= M) { cs[nt][1] = -1e30f; cs[nt][3] = -1e30f; }
            }
        }
        float tm_lo = -1e30f, tm_hi = -1e30f;
#pragma unroll
        for (int nt = 0; nt < 8; nt++) {
            tm_lo = fmaxf(tm_lo, fmaxf(cs[nt][0], cs[nt][1]));
            tm_hi = fmaxf(tm_hi, fmaxf(cs[nt][2], cs[nt][3]));
        }
        tm_lo = fmaxf(tm_lo, __shfl_xor_sync(0xffffffffu, tm_lo, 1));
        tm_lo = fmaxf(tm_lo, __shfl_xor_sync(0xffffffffu, tm_lo, 2));
        tm_hi = fmaxf(tm_hi, __shfl_xor_sync(0xffffffffu, tm_hi, 1));
        tm_hi = fmaxf(tm_hi, __shfl_xor_sync(0xffffffffu, tm_hi, 2));

        const float mn_lo = fmaxf(m_lo, tm_lo);
        const float mn_hi = fmaxf(m_hi, tm_hi);
        const float corr_lo = __expf(m_lo - mn_lo);
        const float corr_hi = __expf(m_hi - mn_hi);
        m_lo = mn_lo; m_hi = mn_hi;

        float rs_lo = 0.f, rs_hi = 0.f;
#pragma unroll
        for (int nt = 0; nt < 8; nt++) {
            cs[nt][0] = __expf(cs[nt][0] - mn_lo);
            cs[nt][1] = __expf(cs[nt][1] - mn_lo);
            cs[nt][2] = __expf(cs[nt][2] - mn_hi);
            cs[nt][3] = __expf(cs[nt][3] - mn_hi);
            rs_lo += cs[nt][0] + cs[nt][1];
            rs_hi += cs[nt][2] + cs[nt][3];
        }
        rs_lo += __shfl_xor_sync(0xffffffffu, rs_lo, 1);
        rs_lo += __shfl_xor_sync(0xffffffffu, rs_lo, 2);
        rs_hi += __shfl_xor_sync(0xffffffffu, rs_hi, 1);
        rs_hi += __shfl_xor_sync(0xffffffffu, rs_hi, 2);
        l_lo = l_lo * corr_lo + rs_lo;
        l_hi = l_hi * corr_hi + rs_hi;

#pragma unroll
        for (int nt = 0; nt < 8; nt++) {
            co[nt][0] *= corr_lo; co[nt][1] *= corr_lo;
            co[nt][2] *= corr_hi; co[nt][3] *= corr_hi;
        }

        // ---- O += P V : A-frag rebuilt from C-frag via quad shuffles ----
#pragma unroll
        for (int ks = 0; ks < 8; ks++) {
            const float v00 = __shfl_sync(0xffffffffu, cs[ks][0], src0);
            const float v01 = __shfl_sync(0xffffffffu, cs[ks][1], src0);
            const float v10 = __shfl_sync(0xffffffffu, cs[ks][2], src0);
            const float v11 = __shfl_sync(0xffffffffu, cs[ks][3], src0);
            const float w00 = __shfl_sync(0xffffffffu, cs[ks][0], src1);
            const float w01 = __shfl_sync(0xffffffffu, cs[ks][1], src1);
            const float w10 = __shfl_sync(0xffffffffu, cs[ks][2], src1);
            const float w11 = __shfl_sync(0xffffffffu, cs[ks][3], src1);
            unsigned a[4];
            a[0] = f2tf(oddt ? v01 : v00);   // P[g    ][ks*8+t]
            a[1] = f2tf(oddt ? v11 : v10);   // P[g+8  ][ks*8+t]
            a[2] = f2tf(oddt ? w01 : w00);   // P[g    ][ks*8+t+4]
            a[3] = f2tf(oddt ? w11 : w10);   // P[g+8  ][ks*8+t+4]
#pragma unroll
            for (int nt = 0; nt < 8; nt++) {
                unsigned b[2];
                b[0] = Vs[(ks * 8 + t    ) * V_STRIDE + nt * 8 + g];
                b[1] = Vs[(ks * 8 + t + 4) * V_STRIDE + nt * 8 + g];
                mma8(co[nt], a, b);
            }
        }
    }

    // ---- normalize + store (row-major g_o) ----
    const float inv_lo = 1.0f / l_lo;
    const float inv_hi = 1.0f / l_hi;
#pragma unroll
    for (int nt = 0; nt < 8; nt++) {
        const int d  = nt * 8 + t * 2;
        const int r0 = q0 + rb + g;
        const int r1 = r0 + 8;
        if (r0 < N_Q)
            *(float2*)&g_o[r0 * CDIM + h * HDIM + d] =
                make_float2(co[nt][0] * inv_lo, co[nt][1] * inv_lo);
        if (r1 < N_Q)
            *(float2*)&g_o[r1 * CDIM + h * HDIM + d] =
                make_float2(co[nt][2] * inv_hi, co[nt][3] * inv_hi);
    }
#undef STAGE_KV
}

// ---------------- launch ---------------------------------------------------
extern "C" void kernel_launch(void* const* d_in, const int* in_sizes, int n_in,
                              void* d_out, int out_size)
{
    const float* x          = (const float*)d_in[0];
    const float* pos        = (const float*)d_in[1];
    const float* mask       = (const float*)d_in[2];
    const float* mask_block = (const float*)d_in[3];
    const float* Wq         = (const float*)d_in[4];
    const float* Wk         = (const float*)d_in[5];
    const float* Wv         = (const float*)d_in[6];
    const float* Wp         = (const float*)d_in[7];
    const float* bp         = (const float*)d_in[8];
    float* out = (float*)d_out;

    cudaFuncSetAttribute(attn_tc, cudaFuncAttributeMaxDynamicSharedMemorySize, ATTN_SMEM);
    cudaFuncSetAttribute(proj_tc, cudaFuncAttributeMaxDynamicSharedMemorySize, PROJ_SMEM);

    pool_kernel<<<64, CDIM>>>(x, mask);
    scan_kernel<<<1, 1024>>>(mask, mask_block);   // also finalizes back token

    // fused Q/K/V projection: blockIdx.z = mode 0/1/2
    dim3 gqkv((N_Q + 127) / 128, CDIM / 64, 3);   // 33 x 6 x 3
    proj_tc<<<gqkv, 256, PROJ_SMEM>>>(0, x, pos, Wq, Wk, Wv, Wp, nullptr, nullptr);

    dim3 gattn((N_Q + 127) / 128, HEADS);         // 33 x 6
    attn_tc<<<gattn, 256, ATTN_SMEM>>>();

    // output projection
    dim3 gout((N_Q + 127) / 128, CDIM / 64, 1);
    proj_tc<<<gout, 256, PROJ_SMEM>>>(3, x, pos, Wq, Wk, Wv, Wp, bp, out);
}

// round 12
// speedup vs baseline: 1.3303x; 1.0192x over previous
#include <cuda_runtime.h>
#include <cuda_bf16.h>
#include <math.h>

#define N_Q   4098
#define N_KV  4099
#define CDIM  384
#define HEADS 6
#define HDIM  64
#define NKV_PAD 4160                 // 65 * 64
#define HSTR_VT (64 * NKV_PAD)       // per-head stride of transposed V

// ---------------- scratch (device globals; allocation-free) ----------------
__device__ __align__(16) float g_pp[64 * CDIM];     // pooling partials
__device__ float  g_cntp[64];                       // count partials
__device__ __align__(16) float g_back[CDIM];        // back token
__device__ int    g_idx[N_KV];                      // kept key -> source row
__device__ int    g_M;                              // number of kept keys
__device__ __align__(16) float g_q[N_Q * CDIM];     // tf32-prerounded, prescaled 1/8
__device__ __align__(16) float g_k[N_KV * CDIM];    // tf32-prerounded
__device__ __align__(16) float g_vt[HEADS * HSTR_VT]; // V transposed [h][d][key], tf32
__device__ __align__(16) float g_o[N_Q * CDIM];

// ---------------- helpers ---------------------------------------------------
__device__ __forceinline__ unsigned f2tf(float x)
{
    unsigned r;
    asm("cvt.rna.tf32.f32 %0, %1;" : "=r"(r) : "f"(x));
    return r;
}

__device__ __forceinline__ void mma8(float* c, const unsigned* a, const unsigned* b)
{
    asm volatile(
        "mma.sync.aligned.m16n8k8.row.col.f32.tf32.tf32.f32 "
        "{%0,%1,%2,%3}, {%4,%5,%6,%7}, {%8,%9}, {%0,%1,%2,%3};\n"
        : "+f"(c[0]), "+f"(c[1]), "+f"(c[2]), "+f"(c[3])
        : "r"(a[0]), "r"(a[1]), "r"(a[2]), "r"(a[3]), "r"(b[0]), "r"(b[1]));
}

__device__ __forceinline__ void ldsm4(uint4& d, unsigned addr)
{
    asm volatile("ldmatrix.sync.aligned.m8n8.x4.shared.b16 {%0,%1,%2,%3}, [%4];"
                 : "=r"(d.x), "=r"(d.y), "=r"(d.z), "=r"(d.w) : "r"(addr));
}

__device__ __forceinline__ void cp16(unsigned dst, const void* src, int sz)
{
    asm volatile("cp.async.ca.shared.global [%0], [%1], 16, %2;"
                 :: "r"(dst), "l"(src), "r"(sz));
}
__device__ __forceinline__ void cp16u(unsigned dst, const void* src)
{
    asm volatile("cp.async.ca.shared.global [%0], [%1], 16;"
                 :: "r"(dst), "l"(src));
}
#define CP_COMMIT() asm volatile("cp.async.commit_group;")
#define CP_WAIT(n)  asm volatile("cp.async.wait_group %0;" :: "n"(n))

// ---------------- 1) background pooling (deterministic, 2-stage) -----------
__global__ void pool_kernel(const float* __restrict__ x, const float* __restrict__ mask)
{
    const int c  = threadIdx.x;            // 384 threads
    const int n0 = blockIdx.x * 64;
    float s = 0.f;
#pragma unroll 8
    for (int i = 0; i < 64; i++) {
        const int n = n0 + i;
        const float rev = (mask[n] < 0.5f) ? 1.f : 0.f;
        s += rev * x[(1 + n) * CDIM + c];
    }
    g_pp[blockIdx.x * CDIM + c] = s;
    if (c == 0) {
        float cc = 0.f;
        for (int i = 0; i < 64; i++) cc += (mask[n0 + i] < 0.5f) ? 1.f : 0.f;
        g_cntp[blockIdx.x] = cc;
    }
}

// ---------------- 2) scan + back-token finalize (fused) --------------------
__global__ void scan_kernel(const float* __restrict__ mask,
                            const float* __restrict__ mask_block)
{
    __shared__ int sc[1024];
    const int t = threadIdx.x;

    if (t < CDIM) {
        float cnt = 0.f;
        for (int b = 0; b < 64; b++) cnt += g_cntp[b];
        float s = 0.f;
        for (int b = 0; b < 64; b++) s += g_pp[b * CDIM + t];
        g_back[t] = s / (cnt + 1e-10f);
    }

    const int base = t * 5;
    int flags[5];
    int cnt = 0;
#pragma unroll
    for (int e = 0; e < 5; e++) {
        int r = base + e;
        int f = 0;
        if (r < N_KV) {
            float mv = (r >= 1 && r <= N_Q - 2) ? mask[r - 1] : mask_block[r];
            f = (mv >= 0.5f) ? 1 : 0;
        }
        flags[e] = f;
        cnt += f;
    }
    sc[t] = cnt;
    __syncthreads();
    for (int off = 1; off < 1024; off <<= 1) {
        int v = (t >= off) ? sc[t - off] : 0;
        __syncthreads();
        sc[t] += v;
        __syncthreads();
    }
    int o = sc[t] - cnt;
#pragma unroll
    for (int e = 0; e < 5; e++)
        if (flags[e]) g_idx[o++] = base + e;
    if (t == 1023) g_M = sc[1023];
}

// ---------------- 2b) zero g_vt tail keys [g_M, NKV_PAD) -------------------
__global__ void vzero_kernel()
{
    const int M = g_M;
    const int tail = NKV_PAD - M;
    const int total = HEADS * 64 * tail;
    for (int i = blockIdx.x * blockDim.x + threadIdx.x; i < total;
         i += gridDim.x * blockDim.x) {
        const int row = i / tail;
        const int key = M + (i - row * tail);
        g_vt[row * NKV_PAD + key] = 0.f;
    }
}

// ---------------- 3) tf32 projection GEMM (ldmatrix mainloop) --------------
// mode 0: q = (x + pos[:N]) @ Wq^T * 1/8    -> g_q   (tf32-rounded)
// mode 1: k = (kv_x[idx] + pos[idx]) @ Wk^T -> g_k   (tf32-rounded, gathered)
// mode 2: v = kv_x[idx] @ Wv^T              -> g_vt  (tf32-rounded, gathered, TRANSPOSED)
// mode 3: o = g_o @ Wp^T + bp               -> d_out (fp32)
#define PROJ_SMEM (2 * (128 * 36 + 64 * 36) * (int)sizeof(unsigned))

__global__ __launch_bounds__(256)
void proj_tc(int base_mode,
             const float* __restrict__ x, const float* __restrict__ pos,
             const float* __restrict__ Wq_, const float* __restrict__ Wk_,
             const float* __restrict__ Wv_, const float* __restrict__ Wp_,
             const float* __restrict__ bias,
             float* __restrict__ out_param)
{
    extern __shared__ unsigned smP[];
    unsigned* smA = smP;                      // [2][128][36]
    unsigned* smW = smP + 2 * 128 * 36;       // [2][64][36]
#define AS(b, r, c) smA[(b) * (128 * 36) + (r) * 36 + (c)]
#define WS(b, r, c) smW[(b) * (64 * 36) + (r) * 36 + (c)]

    const int mode = base_mode + blockIdx.z;
    const int rows = (mode == 1 || mode == 2) ? g_M : N_Q;
    const int m0 = blockIdx.x * 128;
    if (m0 >= rows) return;
    const int j0 = blockIdx.y * 64;

    const float* W =
        (mode == 0) ? Wq_ : (mode == 1) ? Wk_ : (mode == 2) ? Wv_ : Wp_;
    float* outp = (mode == 0) ? g_q : (mode == 1) ? g_k : out_param;

    const int tid  = threadIdx.x;
    const int warp = tid >> 5, lane = tid & 31;
    const int wm = warp >> 1, wn = warp & 1;
    const int g = lane >> 2, t = lane & 3;
    const int m4 = lane >> 3, r8 = lane & 7;
    const unsigned smPB = (unsigned)__cvta_generic_to_shared(smP);

    const unsigned aA0 = smPB + ((wm * 32 + 8 * (m4 & 1) + r8) * 36) * 4u + (m4 >> 1) * 16u;
    const unsigned aW0 = smPB + (2 * 128 * 36 + (wn * 32 + 8 * (m4 >> 1) + r8) * 36) * 4u
                       + (m4 & 1) * 16u;

    const float* pA[4];
    const float* pP[4];
    int rA[4];
#pragma unroll
    for (int i = 0; i < 4; i++) {
        const int lin = tid + i * 256;
        rA[i] = lin >> 3;
        const int mg = m0 + rA[i];
        pA[i] = nullptr; pP[i] = nullptr;
        if (mg < rows) {
            if (mode == 0) {
                pA[i] = x + mg * CDIM;
                pP[i] = pos + mg * CDIM;
            } else if (mode == 3) {
                pA[i] = g_o + mg * CDIM;
            } else {
                const int src = g_idx[mg];
                pA[i] = (src < N_Q) ? (x + src * CDIM) : g_back;
                if (mode == 1) pP[i] = pos + src * CDIM;
            }
        }
    }
    const float* pW[2];
    int rW[2];
#pragma unroll
    for (int i = 0; i < 2; i++) {
        const int lin = tid + i * 256;
        rW[i] = lin >> 3;
        pW[i] = W + (j0 + rW[i]) * CDIM;
    }
    const int cA = (tid & 7) * 4;

    float4 aReg[4], pReg[4], wReg[2];

#define PREFETCH(kt)                                                          \
    do {                                                                      \
        _Pragma("unroll")                                                     \
        for (int i = 0; i < 4; i++) {                                         \
            aReg[i] = pA[i] ? *(const float4*)(pA[i] + (kt) + cA)             \
                            : make_float4(0.f, 0.f, 0.f, 0.f);                \
            pReg[i] = pP[i] ? *(const float4*)(pP[i] + (kt) + cA)             \
                            : make_float4(0.f, 0.f, 0.f, 0.f);                \
        }                                                                     \
        _Pragma("unroll")                                                     \
        for (int i = 0; i < 2; i++)                                           \
            wReg[i] = *(const float4*)(pW[i] + (kt) + cA);                    \
    } while (0)

#define STORE(buf)                                                            \
    do {                                                                      \
        _Pragma("unroll")                                                     \
        for (int i = 0; i < 4; i++) {                                         \
            AS(buf, rA[i], cA + 0) = f2tf(aReg[i].x + pReg[i].x);             \
            AS(buf, rA[i], cA + 1) = f2tf(aReg[i].y + pReg[i].y);             \
            AS(buf, rA[i], cA + 2) = f2tf(aReg[i].z + pReg[i].z);             \
            AS(buf, rA[i], cA + 3) = f2tf(aReg[i].w + pReg[i].w);             \
        }                                                                     \
        _Pragma("unroll")                                                     \
        for (int i = 0; i < 2; i++) {                                         \
            WS(buf, rW[i], cA + 0) = f2tf(wReg[i].x);                         \
            WS(buf, rW[i], cA + 1) = f2tf(wReg[i].y);                         \
            WS(buf, rW[i], cA + 2) = f2tf(wReg[i].z);                         \
            WS(buf, rW[i], cA + 3) = f2tf(wReg[i].w);                         \
        }                                                                     \
    } while (0)

    float acc[2][4][4] = {};

    PREFETCH(0);
    STORE(0);
    __syncthreads();

    const int NT = CDIM / 32;              // 12
    for (int kt = 0; kt < NT; kt++) {
        const int cur = kt & 1;
        if (kt + 1 < NT) PREFETCH((kt + 1) * 32);

        const unsigned aAb = aA0 + cur * (128 * 36 * 4);
        const unsigned aWb = aW0 + cur * (64 * 36 * 4);
#pragma unroll
        for (int ks = 0; ks < 4; ks++) {
            uint4 av[2], bv[2];
#pragma unroll
            for (int mt = 0; mt < 2; mt++)
                ldsm4(av[mt], aAb + mt * (16 * 36 * 4) + ks * 32);
#pragma unroll
            for (int np = 0; np < 2; np++)
                ldsm4(bv[np], aWb + np * (16 * 36 * 4) + ks * 32);
#pragma unroll
            for (int mt = 0; mt < 2; mt++)
#pragma unroll
                for (int np = 0; np < 2; np++) {
                    mma8(acc[mt][2 * np    ], (const unsigned*)&av[mt], (const unsigned*)&bv[np].x);
                    mma8(acc[mt][2 * np + 1], (const unsigned*)&av[mt], (const unsigned*)&bv[np].z);
                }
        }

        if (kt + 1 < NT) STORE(cur ^ 1);
        __syncthreads();
    }

#pragma unroll
    for (int mt = 0; mt < 2; mt++) {
#pragma unroll
        for (int nt = 0; nt < 4; nt++) {
            const int col = j0 + wn * 32 + nt * 8 + t * 2;
            const int r0 = m0 + wm * 32 + mt * 16 + g;
            const int r1 = r0 + 8;
            float* a = acc[mt][nt];
            if (mode == 3) {
                const float b0 = bias ? bias[col]     : 0.f;
                const float b1 = bias ? bias[col + 1] : 0.f;
                if (r0 < rows)
                    *(float2*)&outp[r0 * CDIM + col] = make_float2(a[0] + b0, a[1] + b1);
                if (r1 < rows)
                    *(float2*)&outp[r1 * CDIM + col] = make_float2(a[2] + b0, a[3] + b1);
            } else if (mode == 2) {
                // transposed store: g_vt[h][d][key]
                float* vb = g_vt + (col >> 6) * HSTR_VT + (col & 63) * NKV_PAD;
                if (r0 < rows) {
                    vb[r0]           = __uint_as_float(f2tf(a[0]));
                    vb[NKV_PAD + r0] = __uint_as_float(f2tf(a[1]));
                }
                if (r1 < rows) {
                    vb[r1]           = __uint_as_float(f2tf(a[2]));
                    vb[NKV_PAD + r1] = __uint_as_float(f2tf(a[3]));
                }
            } else {
                const float oscale = (mode == 0) ? 0.125f : 1.0f;
                if (r0 < rows) {
                    float2 v = make_float2(__uint_as_float(f2tf(a[0] * oscale)),
                                           __uint_as_float(f2tf(a[1] * oscale)));
                    *(float2*)&outp[r0 * CDIM + col] = v;
                }
                if (r1 < rows) {
                    float2 v = make_float2(__uint_as_float(f2tf(a[2] * oscale)),
                                           __uint_as_float(f2tf(a[3] * oscale)));
                    *(float2*)&outp[r1 * CDIM + col] = v;
                }
            }
        }
    }
#undef AS
#undef WS
#undef PREFETCH
#undef STORE
}

// ---------------- 4) tf32 flash attention (all-ldmatrix, no P smem) --------
// grid (33, HEADS), block 256 (8 warps x 16 q-rows each), 2 CTAs/SM
// smem (words): Q[128][68] | K[2][64][68] | Vt[2][64][68]   = 104.4 KB
#define AT_STRIDE 68
#define K_OFF  8704
#define VT_OFF 17408
#define KV_BUF 4352                        // 64*68 words per buffer
#define ATTN_SMEM ((VT_OFF + 2 * KV_BUF) * (int)sizeof(unsigned))

__global__ __launch_bounds__(256, 2)
void attn_tc()
{
    extern __shared__ unsigned sm[];

    const int h  = blockIdx.y;
    const int q0 = blockIdx.x * 128;
    const int M  = g_M;
    const int tid = threadIdx.x, warp = tid >> 5, lane = tid & 31;
    const int g = lane >> 2, t = lane & 3;
    const int rb = warp * 16;
    const int m4 = lane >> 3, r8 = lane & 7;
    const unsigned smB = (unsigned)__cvta_generic_to_shared(sm);

    // ldmatrix lane-base addresses (bytes)
    const unsigned aQ  = smB + ((rb + 8 * (m4 & 1) + r8) * AT_STRIDE) * 4u + (m4 >> 1) * 16u;
    const unsigned aKc = ((8 * (m4 >> 1) + r8) * AT_STRIDE) * 4u + (m4 & 1) * 16u;
    // quad-shuffle source lanes for PV A-frag rebuild
    const int src0 = (lane & 28) | (t >> 1);
    const int src1 = src0 + 2;
    const bool oddt = (t & 1);

    // ---- async stage Q tile [128 q][64 d] ----
#pragma unroll
    for (int i = 0; i < 8; i++) {
        const int lin = tid + i * 256;
        const int r = lin >> 4, c4 = (lin & 15) * 4;
        cp16(smB + (r * AT_STRIDE + c4) * 4u,
             &g_q[(q0 + r) * CDIM + h * HDIM + c4],
             (q0 + r < N_Q) ? 16 : 0);
    }

#define STAGE_KV(kt, buf)                                                     \
    do {                                                                      \
        const float* vsrc = g_vt + h * HSTR_VT + (kt) * 64;                   \
        _Pragma("unroll")                                                     \
        for (int i = 0; i < 4; i++) {                                         \
            const int lin = tid + i * 256;                                    \
            const int r = lin >> 4, c4 = (lin & 15) * 4;                      \
            const int kg = (kt) * 64 + r;                                     \
            cp16(smB + ((K_OFF + (buf) * KV_BUF) + r * AT_STRIDE + c4) * 4u,  \
                 &g_k[kg * CDIM + h * HDIM + c4], (kg < M) ? 16 : 0);         \
            cp16u(smB + ((VT_OFF + (buf) * KV_BUF) + r * AT_STRIDE + c4) * 4u,\
                  vsrc + r * NKV_PAD + c4);                                   \
        }                                                                     \
    } while (0)

    const int nT = (M + 63) >> 6;
    STAGE_KV(0, 0);
    CP_COMMIT();                           // group: Q + tile0

    float m_lo = -1e30f, m_hi = -1e30f, l_lo = 0.f, l_hi = 0.f;
    float co[8][4] = {};

    for (int kt = 0; kt < nT; kt++) {
        const int cur = kt & 1;
        __syncthreads();                   // all warps done with buffer cur^1
        if (kt + 1 < nT) {
            STAGE_KV(kt + 1, cur ^ 1);
            CP_COMMIT();
            CP_WAIT(1);
        } else {
            CP_WAIT(0);
        }
        __syncthreads();

        const unsigned kBase = smB + (K_OFF  + cur * KV_BUF) * 4u + aKc;
        const unsigned vBase = smB + (VT_OFF + cur * KV_BUF) * 4u + aKc;

        // ---- S = Q K^T via ldmatrix ----
        float cs[8][4] = {};
#pragma unroll
        for (int ks = 0; ks < 8; ks++) {
            uint4 a;
            ldsm4(a, aQ + ks * 32);
#pragma unroll
            for (int j = 0; j < 4; j++) {
                uint4 b;
                ldsm4(b, kBase + j * (16 * AT_STRIDE * 4) + ks * 32);
                mma8(cs[2 * j    ], (const unsigned*)&a, (const unsigned*)&b.x);
                mma8(cs[2 * j + 1], (const unsigned*)&a, (const unsigned*)&b.z);
            }
        }

        // ---- online softmax ----
        if (kt == nT - 1) {                // tail tile: mask invalid keys
#pragma unroll
            for (int nt = 0; nt < 8; nt++) {
                const int c0 = kt * 64 + nt * 8 + t * 2;
                if (c0     >= M) { cs[nt][0] = -1e30f; cs[nt][2] = -1e30f; }
                if (c0 + 1 >= M) { cs[nt][1] = -1e30f; cs[nt][3] = -1e30f; }
            }
        }
        float tm_lo = -1e30f, tm_hi = -1e30f;
#pragma unroll
        for (int nt = 0; nt < 8; nt++) {
            tm_lo = fmaxf(tm_lo, fmaxf(cs[nt][0], cs[nt][1]));
            tm_hi = fmaxf(tm_hi, fmaxf(cs[nt][2], cs[nt][3]));
        }
        tm_lo = fmaxf(tm_lo, __shfl_xor_sync(0xffffffffu, tm_lo, 1));
        tm_lo = fmaxf(tm_lo, __shfl_xor_sync(0xffffffffu, tm_lo, 2));
        tm_hi = fmaxf(tm_hi, __shfl_xor_sync(0xffffffffu, tm_hi, 1));
        tm_hi = fmaxf(tm_hi, __shfl_xor_sync(0xffffffffu, tm_hi, 2));

        const float mn_lo = fmaxf(m_lo, tm_lo);
        const float mn_hi = fmaxf(m_hi, tm_hi);
        const float corr_lo = __expf(m_lo - mn_lo);
        const float corr_hi = __expf(m_hi - mn_hi);
        m_lo = mn_lo; m_hi = mn_hi;

        float rs_lo = 0.f, rs_hi = 0.f;
#pragma unroll
        for (int nt = 0; nt < 8; nt++) {
            cs[nt][0] = __expf(cs[nt][0] - mn_lo);
            cs[nt][1] = __expf(cs[nt][1] - mn_lo);
            cs[nt][2] = __expf(cs[nt][2] - mn_hi);
            cs[nt][3] = __expf(cs[nt][3] - mn_hi);
            rs_lo += cs[nt][0] + cs[nt][1];
            rs_hi += cs[nt][2] + cs[nt][3];
        }
        rs_lo += __shfl_xor_sync(0xffffffffu, rs_lo, 1);
        rs_lo += __shfl_xor_sync(0xffffffffu, rs_lo, 2);
        rs_hi += __shfl_xor_sync(0xffffffffu, rs_hi, 1);
        rs_hi += __shfl_xor_sync(0xffffffffu, rs_hi, 2);
        l_lo = l_lo * corr_lo + rs_lo;
        l_hi = l_hi * corr_hi + rs_hi;

#pragma unroll
        for (int nt = 0; nt < 8; nt++) {
            co[nt][0] *= corr_lo; co[nt][1] *= corr_lo;
            co[nt][2] *= corr_hi; co[nt][3] *= corr_hi;
        }

        // ---- O += P V : A-frag via quad shuffles, B-frag via ldmatrix(Vt) --
#pragma unroll
        for (int ks = 0; ks < 8; ks++) {
            const float v00 = __shfl_sync(0xffffffffu, cs[ks][0], src0);
            const float v01 = __shfl_sync(0xffffffffu, cs[ks][1], src0);
            const float v10 = __shfl_sync(0xffffffffu, cs[ks][2], src0);
            const float v11 = __shfl_sync(0xffffffffu, cs[ks][3], src0);
            const float w00 = __shfl_sync(0xffffffffu, cs[ks][0], src1);
            const float w01 = __shfl_sync(0xffffffffu, cs[ks][1], src1);
            const float w10 = __shfl_sync(0xffffffffu, cs[ks][2], src1);
            const float w11 = __shfl_sync(0xffffffffu, cs[ks][3], src1);
            unsigned a[4];
            a[0] = f2tf(oddt ? v01 : v00);
            a[1] = f2tf(oddt ? v11 : v10);
            a[2] = f2tf(oddt ? w01 : w00);
            a[3] = f2tf(oddt ? w11 : w10);
#pragma unroll
            for (int j = 0; j < 4; j++) {
                uint4 b;
                ldsm4(b, vBase + j * (16 * AT_STRIDE * 4) + ks * 32);
                mma8(co[2 * j    ], a, (const unsigned*)&b.x);
                mma8(co[2 * j + 1], a, (const unsigned*)&b.z);
            }
        }
    }

    // ---- normalize + store (row-major g_o) ----
    const float inv_lo = 1.0f / l_lo;
    const float inv_hi = 1.0f / l_hi;
#pragma unroll
    for (int nt = 0; nt < 8; nt++) {
        const int d  = nt * 8 + t * 2;
        const int r0 = q0 + rb + g;
        const int r1 = r0 + 8;
        if (r0 < N_Q)
            *(float2*)&g_o[r0 * CDIM + h * HDIM + d] =
                make_float2(co[nt][0] * inv_lo, co[nt][1] * inv_lo);
        if (r1 < N_Q)
            *(float2*)&g_o[r1 * CDIM + h * HDIM + d] =
                make_float2(co[nt][2] * inv_hi, co[nt][3] * inv_hi);
    }
#undef STAGE_KV
}

// ---------------- launch ---------------------------------------------------
extern "C" void kernel_launch(void* const* d_in, const int* in_sizes, int n_in,
                              void* d_out, int out_size)
{
    const float* x          = (const float*)d_in[0];
    const float* pos        = (const float*)d_in[1];
    const float* mask       = (const float*)d_in[2];
    const float* mask_block = (const float*)d_in[3];
    const float* Wq         = (const float*)d_in[4];
    const float* Wk         = (const float*)d_in[5];
    const float* Wv         = (const float*)d_in[6];
    const float* Wp         = (const float*)d_in[7];
    const float* bp         = (const float*)d_in[8];
    float* out = (float*)d_out;

    cudaFuncSetAttribute(attn_tc, cudaFuncAttributeMaxDynamicSharedMemorySize, ATTN_SMEM);
    cudaFuncSetAttribute(proj_tc, cudaFuncAttributeMaxDynamicSharedMemorySize, PROJ_SMEM);

    pool_kernel<<<64, CDIM>>>(x, mask);
    scan_kernel<<<1, 1024>>>(mask, mask_block);   // also finalizes back token
    vzero_kernel<<<128, 256>>>();                 // zero Vt tail keys

    // fused Q/K/V projection: blockIdx.z = mode 0/1/2
    dim3 gqkv((N_Q + 127) / 128, CDIM / 64, 3);   // 33 x 6 x 3
    proj_tc<<<gqkv, 256, PROJ_SMEM>>>(0, x, pos, Wq, Wk, Wv, Wp, nullptr, nullptr);

    dim3 gattn((N_Q + 127) / 128, HEADS);         // 33 x 6
    attn_tc<<<gattn, 256, ATTN_SMEM>>>();

    // output projection
    dim3 gout((N_Q + 127) / 128, CDIM / 64, 1);
    proj_tc<<<gout, 256, PROJ_SMEM>>>(3, x, pos, Wq, Wk, Wv, Wp, bp, out);
}

// round 14
// speedup vs baseline: 1.5237x; 1.1454x over previous
#include <cuda_runtime.h>
#include <cuda_bf16.h>
#include <math.h>

#define N_Q   4098
#define N_KV  4099
#define CDIM  384
#define HEADS 6
#define HDIM  64
#define NKV_PAD 4160                 // 65 * 64
#define HSTR_VT (64 * NKV_PAD)       // per-head stride of transposed V
#define NITEMS 198                   // 33 qtiles * 6 heads
#define NSPLIT 3

// ---------------- scratch (device globals; allocation-free) ----------------
__device__ __align__(16) float g_pp[64 * CDIM];     // pooling partials
__device__ float  g_cntp[64];                       // count partials
__device__ __align__(16) float g_back[CDIM];        // back token
__device__ int    g_idx[N_KV];                      // kept key -> source row
__device__ int    g_M;                              // number of kept keys
__device__ __align__(16) float g_q[N_Q * CDIM];     // tf32-prerounded, prescaled 1/8
__device__ __align__(16) float g_k[N_KV * CDIM];    // tf32-prerounded
__device__ __align__(16) float g_vt[HEADS * HSTR_VT]; // V transposed [h][d][key], tf32
__device__ __align__(16) float g_o[N_Q * CDIM];
// split-KV partials
__device__ __align__(16) float g_po[NSPLIT * NITEMS * 128 * 64]; // unnormalized O
__device__ float g_pm[NSPLIT * NITEMS * 128];                    // row max
__device__ float g_pl[NSPLIT * NITEMS * 128];                    // row sum

// ---------------- helpers ---------------------------------------------------
__device__ __forceinline__ unsigned f2tf(float x)
{
    unsigned r;
    asm("cvt.rna.tf32.f32 %0, %1;" : "=r"(r) : "f"(x));
    return r;
}

__device__ __forceinline__ void mma8(float* c, const unsigned* a, const unsigned* b)
{
    asm volatile(
        "mma.sync.aligned.m16n8k8.row.col.f32.tf32.tf32.f32 "
        "{%0,%1,%2,%3}, {%4,%5,%6,%7}, {%8,%9}, {%0,%1,%2,%3};\n"
        : "+f"(c[0]), "+f"(c[1]), "+f"(c[2]), "+f"(c[3])
        : "r"(a[0]), "r"(a[1]), "r"(a[2]), "r"(a[3]), "r"(b[0]), "r"(b[1]));
}

__device__ __forceinline__ void ldsm4(uint4& d, unsigned addr)
{
    asm volatile("ldmatrix.sync.aligned.m8n8.x4.shared.b16 {%0,%1,%2,%3}, [%4];"
                 : "=r"(d.x), "=r"(d.y), "=r"(d.z), "=r"(d.w) : "r"(addr));
}

__device__ __forceinline__ void cp16(unsigned dst, const void* src, int sz)
{
    asm volatile("cp.async.ca.shared.global [%0], [%1], 16, %2;"
                 :: "r"(dst), "l"(src), "r"(sz));
}
__device__ __forceinline__ void cp16u(unsigned dst, const void* src)
{
    asm volatile("cp.async.ca.shared.global [%0], [%1], 16;"
                 :: "r"(dst), "l"(src));
}
#define CP_COMMIT() asm volatile("cp.async.commit_group;")
#define CP_WAIT(n)  asm volatile("cp.async.wait_group %0;" :: "n"(n))

// ---------------- 1) background pooling (deterministic, 2-stage) -----------
__global__ void pool_kernel(const float* __restrict__ x, const float* __restrict__ mask)
{
    const int c  = threadIdx.x;            // 384 threads
    const int n0 = blockIdx.x * 64;
    float s = 0.f;
#pragma unroll 8
    for (int i = 0; i < 64; i++) {
        const int n = n0 + i;
        const float rev = (mask[n] < 0.5f) ? 1.f : 0.f;
        s += rev * x[(1 + n) * CDIM + c];
    }
    g_pp[blockIdx.x * CDIM + c] = s;
    if (c == 0) {
        float cc = 0.f;
        for (int i = 0; i < 64; i++) cc += (mask[n0 + i] < 0.5f) ? 1.f : 0.f;
        g_cntp[blockIdx.x] = cc;
    }
}

// ---------------- 2) scan + back-token finalize (fused) --------------------
__global__ void scan_kernel(const float* __restrict__ mask,
                            const float* __restrict__ mask_block)
{
    __shared__ int sc[1024];
    const int t = threadIdx.x;

    if (t < CDIM) {
        float cnt = 0.f;
        for (int b = 0; b < 64; b++) cnt += g_cntp[b];
        float s = 0.f;
        for (int b = 0; b < 64; b++) s += g_pp[b * CDIM + t];
        g_back[t] = s / (cnt + 1e-10f);
    }

    const int base = t * 5;
    int flags[5];
    int cnt = 0;
#pragma unroll
    for (int e = 0; e < 5; e++) {
        int r = base + e;
        int f = 0;
        if (r < N_KV) {
            float mv = (r >= 1 && r <= N_Q - 2) ? mask[r - 1] : mask_block[r];
            f = (mv >= 0.5f) ? 1 : 0;
        }
        flags[e] = f;
        cnt += f;
    }
    sc[t] = cnt;
    __syncthreads();
    for (int off = 1; off < 1024; off <<= 1) {
        int v = (t >= off) ? sc[t - off] : 0;
        __syncthreads();
        sc[t] += v;
        __syncthreads();
    }
    int o = sc[t] - cnt;
#pragma unroll
    for (int e = 0; e < 5; e++)
        if (flags[e]) g_idx[o++] = base + e;
    if (t == 1023) g_M = sc[1023];
}

// ---------------- 2b) zero g_vt tail keys [g_M, NKV_PAD) -------------------
__global__ void vzero_kernel()
{
    const int M = g_M;
    const int tail = NKV_PAD - M;
    const int total = HEADS * 64 * tail;
    for (int i = blockIdx.x * blockDim.x + threadIdx.x; i < total;
         i += gridDim.x * blockDim.x) {
        const int row = i / tail;
        const int key = M + (i - row * tail);
        g_vt[row * NKV_PAD + key] = 0.f;
    }
}

// ---------------- 3) tf32 projection GEMM (ldmatrix mainloop) --------------
// mode 0: q -> g_q; mode 1: k -> g_k; mode 2: v -> g_vt (transposed);
// mode 3: o = g_o @ Wp^T + bp -> d_out
#define PROJ_SMEM (2 * (128 * 36 + 64 * 36) * (int)sizeof(unsigned))

__global__ __launch_bounds__(256)
void proj_tc(int base_mode,
             const float* __restrict__ x, const float* __restrict__ pos,
             const float* __restrict__ Wq_, const float* __restrict__ Wk_,
             const float* __restrict__ Wv_, const float* __restrict__ Wp_,
             const float* __restrict__ bias,
             float* __restrict__ out_param)
{
    extern __shared__ unsigned smP[];
    unsigned* smA = smP;                      // [2][128][36]
    unsigned* smW = smP + 2 * 128 * 36;       // [2][64][36]
#define AS(b, r, c) smA[(b) * (128 * 36) + (r) * 36 + (c)]
#define WS(b, r, c) smW[(b) * (64 * 36) + (r) * 36 + (c)]

    const int mode = base_mode + blockIdx.z;
    const int rows = (mode == 1 || mode == 2) ? g_M : N_Q;
    const int m0 = blockIdx.x * 128;
    if (m0 >= rows) return;
    const int j0 = blockIdx.y * 64;

    const float* W =
        (mode == 0) ? Wq_ : (mode == 1) ? Wk_ : (mode == 2) ? Wv_ : Wp_;
    float* outp = (mode == 0) ? g_q : (mode == 1) ? g_k : out_param;

    const int tid  = threadIdx.x;
    const int warp = tid >> 5, lane = tid & 31;
    const int wm = warp >> 1, wn = warp & 1;
    const int g = lane >> 2, t = lane & 3;
    const int m4 = lane >> 3, r8 = lane & 7;
    const unsigned smPB = (unsigned)__cvta_generic_to_shared(smP);

    const unsigned aA0 = smPB + ((wm * 32 + 8 * (m4 & 1) + r8) * 36) * 4u + (m4 >> 1) * 16u;
    const unsigned aW0 = smPB + (2 * 128 * 36 + (wn * 32 + 8 * (m4 >> 1) + r8) * 36) * 4u
                       + (m4 & 1) * 16u;

    const float* pA[4];
    const float* pP[4];
    int rA[4];
#pragma unroll
    for (int i = 0; i < 4; i++) {
        const int lin = tid + i * 256;
        rA[i] = lin >> 3;
        const int mg = m0 + rA[i];
        pA[i] = nullptr; pP[i] = nullptr;
        if (mg < rows) {
            if (mode == 0) {
                pA[i] = x + mg * CDIM;
                pP[i] = pos + mg * CDIM;
            } else if (mode == 3) {
                pA[i] = g_o + mg * CDIM;
            } else {
                const int src = g_idx[mg];
                pA[i] = (src < N_Q) ? (x + src * CDIM) : g_back;
                if (mode == 1) pP[i] = pos + src * CDIM;
            }
        }
    }
    const float* pW[2];
    int rW[2];
#pragma unroll
    for (int i = 0; i < 2; i++) {
        const int lin = tid + i * 256;
        rW[i] = lin >> 3;
        pW[i] = W + (j0 + rW[i]) * CDIM;
    }
    const int cA = (tid & 7) * 4;

    float4 aReg[4], pReg[4], wReg[2];

#define PREFETCH(kt)                                                          \
    do {                                                                      \
        _Pragma("unroll")                                                     \
        for (int i = 0; i < 4; i++) {                                         \
            aReg[i] = pA[i] ? *(const float4*)(pA[i] + (kt) + cA)             \
                            : make_float4(0.f, 0.f, 0.f, 0.f);                \
            pReg[i] = pP[i] ? *(const float4*)(pP[i] + (kt) + cA)             \
                            : make_float4(0.f, 0.f, 0.f, 0.f);                \
        }                                                                     \
        _Pragma("unroll")                                                     \
        for (int i = 0; i < 2; i++)                                           \
            wReg[i] = *(const float4*)(pW[i] + (kt) + cA);                    \
    } while (0)

#define STORE(buf)                                                            \
    do {                                                                      \
        _Pragma("unroll")                                                     \
        for (int i = 0; i < 4; i++) {                                         \
            AS(buf, rA[i], cA + 0) = f2tf(aReg[i].x + pReg[i].x);             \
            AS(buf, rA[i], cA + 1) = f2tf(aReg[i].y + pReg[i].y);             \
            AS(buf, rA[i], cA + 2) = f2tf(aReg[i].z + pReg[i].z);             \
            AS(buf, rA[i], cA + 3) = f2tf(aReg[i].w + pReg[i].w);             \
        }                                                                     \
        _Pragma("unroll")                                                     \
        for (int i = 0; i < 2; i++) {                                         \
            WS(buf, rW[i], cA + 0) = f2tf(wReg[i].x);                         \
            WS(buf, rW[i], cA + 1) = f2tf(wReg[i].y);                         \
            WS(buf, rW[i], cA + 2) = f2tf(wReg[i].z);                         \
            WS(buf, rW[i], cA + 3) = f2tf(wReg[i].w);                         \
        }                                                                     \
    } while (0)

    float acc[2][4][4] = {};

    PREFETCH(0);
    STORE(0);
    __syncthreads();

    const int NT = CDIM / 32;              // 12
    for (int kt = 0; kt < NT; kt++) {
        const int cur = kt & 1;
        if (kt + 1 < NT) PREFETCH((kt + 1) * 32);

        const unsigned aAb = aA0 + cur * (128 * 36 * 4);
        const unsigned aWb = aW0 + cur * (64 * 36 * 4);
#pragma unroll
        for (int ks = 0; ks < 4; ks++) {
            uint4 av[2], bv[2];
#pragma unroll
            for (int mt = 0; mt < 2; mt++)
                ldsm4(av[mt], aAb + mt * (16 * 36 * 4) + ks * 32);
#pragma unroll
            for (int np = 0; np < 2; np++)
                ldsm4(bv[np], aWb + np * (16 * 36 * 4) + ks * 32);
#pragma unroll
            for (int mt = 0; mt < 2; mt++)
#pragma unroll
                for (int np = 0; np < 2; np++) {
                    mma8(acc[mt][2 * np    ], (const unsigned*)&av[mt], (const unsigned*)&bv[np].x);
                    mma8(acc[mt][2 * np + 1], (const unsigned*)&av[mt], (const unsigned*)&bv[np].z);
                }
        }

        if (kt + 1 < NT) STORE(cur ^ 1);
        __syncthreads();
    }

#pragma unroll
    for (int mt = 0; mt < 2; mt++) {
#pragma unroll
        for (int nt = 0; nt < 4; nt++) {
            const int col = j0 + wn * 32 + nt * 8 + t * 2;
            const int r0 = m0 + wm * 32 + mt * 16 + g;
            const int r1 = r0 + 8;
            float* a = acc[mt][nt];
            if (mode == 3) {
                const float b0 = bias ? bias[col]     : 0.f;
                const float b1 = bias ? bias[col + 1] : 0.f;
                if (r0 < rows)
                    *(float2*)&outp[r0 * CDIM + col] = make_float2(a[0] + b0, a[1] + b1);
                if (r1 < rows)
                    *(float2*)&outp[r1 * CDIM + col] = make_float2(a[2] + b0, a[3] + b1);
            } else if (mode == 2) {
                float* vb = g_vt + (col >> 6) * HSTR_VT + (col & 63) * NKV_PAD;
                if (r0 < rows) {
                    vb[r0]           = __uint_as_float(f2tf(a[0]));
                    vb[NKV_PAD + r0] = __uint_as_float(f2tf(a[1]));
                }
                if (r1 < rows) {
                    vb[r1]           = __uint_as_float(f2tf(a[2]));
                    vb[NKV_PAD + r1] = __uint_as_float(f2tf(a[3]));
                }
            } else {
                const float oscale = (mode == 0) ? 0.125f : 1.0f;
                if (r0 < rows) {
                    float2 v = make_float2(__uint_as_float(f2tf(a[0] * oscale)),
                                           __uint_as_float(f2tf(a[1] * oscale)));
                    *(float2*)&outp[r0 * CDIM + col] = v;
                }
                if (r1 < rows) {
                    float2 v = make_float2(__uint_as_float(f2tf(a[2] * oscale)),
                                           __uint_as_float(f2tf(a[3] * oscale)));
                    *(float2*)&outp[r1 * CDIM + col] = v;
                }
            }
        }
    }
#undef AS
#undef WS
#undef PREFETCH
#undef STORE
}

// ---------------- 4) tf32 flash attention (split-KV, all-ldmatrix) ---------
// grid (33, HEADS, NSPLIT), block 256; each split owns ~nT/3 key tiles and
// writes unnormalized partial O + per-row (m, l) to global scratch.
#define AT_STRIDE 68
#define K_OFF  8704
#define VT_OFF 17408
#define KV_BUF 4352
#define ATTN_SMEM ((VT_OFF + 2 * KV_BUF) * (int)sizeof(unsigned))

__global__ __launch_bounds__(256, 2)
void attn_tc()
{
    extern __shared__ unsigned sm[];

    const int h  = blockIdx.y;
    const int q0 = blockIdx.x * 128;
    const int z  = blockIdx.z;
    const int M  = g_M;
    const int nT = (M + 63) >> 6;
    const int per = (nT + NSPLIT - 1) / NSPLIT;
    const int t0 = z * per;
    const int t1 = min(nT, t0 + per);

    const int tid = threadIdx.x, warp = tid >> 5, lane = tid & 31;
    const int g = lane >> 2, t = lane & 3;
    const int rb = warp * 16;
    const int m4 = lane >> 3, r8 = lane & 7;
    const unsigned smB = (unsigned)__cvta_generic_to_shared(sm);

    const unsigned aQ  = smB + ((rb + 8 * (m4 & 1) + r8) * AT_STRIDE) * 4u + (m4 >> 1) * 16u;
    const unsigned aKc = ((8 * (m4 >> 1) + r8) * AT_STRIDE) * 4u + (m4 & 1) * 16u;
    const int src0 = (lane & 28) | (t >> 1);
    const int src1 = src0 + 2;
    const bool oddt = (t & 1);

#define STAGE_KV(kt, buf)                                                     \
    do {                                                                      \
        const float* vsrc = g_vt + h * HSTR_VT + (kt) * 64;                   \
        _Pragma("unroll")                                                     \
        for (int i = 0; i < 4; i++) {                                         \
            const int lin = tid + i * 256;                                    \
            const int r = lin >> 4, c4 = (lin & 15) * 4;                      \
            const int kg = (kt) * 64 + r;                                     \
            cp16(smB + ((K_OFF + (buf) * KV_BUF) + r * AT_STRIDE + c4) * 4u,  \
                 &g_k[kg * CDIM + h * HDIM + c4], (kg < M) ? 16 : 0);         \
            cp16u(smB + ((VT_OFF + (buf) * KV_BUF) + r * AT_STRIDE + c4) * 4u,\
                  vsrc + r * NKV_PAD + c4);                                   \
        }                                                                     \
    } while (0)

    float m_lo = -1e30f, m_hi = -1e30f, l_lo = 0.f, l_hi = 0.f;
    float co[8][4] = {};

    if (t0 < t1) {
        // ---- stage Q tile [128 q][64 d] ----
#pragma unroll
        for (int i = 0; i < 8; i++) {
            const int lin = tid + i * 256;
            const int r = lin >> 4, c4 = (lin & 15) * 4;
            cp16(smB + (r * AT_STRIDE + c4) * 4u,
                 &g_q[(q0 + r) * CDIM + h * HDIM + c4],
                 (q0 + r < N_Q) ? 16 : 0);
        }
        STAGE_KV(t0, 0);
        CP_COMMIT();

        for (int kt = t0; kt < t1; kt++) {
            const int cur = (kt - t0) & 1;
            __syncthreads();
            if (kt + 1 < t1) {
                STAGE_KV(kt + 1, cur ^ 1);
                CP_COMMIT();
                CP_WAIT(1);
            } else {
                CP_WAIT(0);
            }
            __syncthreads();

            const unsigned kBase = smB + (K_OFF  + cur * KV_BUF) * 4u + aKc;
            const unsigned vBase = smB + (VT_OFF + cur * KV_BUF) * 4u + aKc;

            // ---- S = Q K^T via ldmatrix ----
            float cs[8][4] = {};
#pragma unroll
            for (int ks = 0; ks < 8; ks++) {
                uint4 a;
                ldsm4(a, aQ + ks * 32);
#pragma unroll
                for (int j = 0; j < 4; j++) {
                    uint4 b;
                    ldsm4(b, kBase + j * (16 * AT_STRIDE * 4) + ks * 32);
                    mma8(cs[2 * j    ], (const unsigned*)&a, (const unsigned*)&b.x);
                    mma8(cs[2 * j + 1], (const unsigned*)&a, (const unsigned*)&b.z);
                }
            }

            // ---- online softmax ----
            if (kt == nT - 1) {            // global tail tile: mask invalid keys
#pragma unroll
                for (int nt = 0; nt < 8; nt++) {
                    const int c0 = kt * 64 + nt * 8 + t * 2;
                    if (c0     >= M) { cs[nt][0] = -1e30f; cs[nt][2] = -1e30f; }
                    if (c0 + 1 >= M) { cs[nt][1] = -1e30f; cs[nt][3] = -1e30f; }
                }
            }
            float tm_lo = -1e30f, tm_hi = -1e30f;
#pragma unroll
            for (int nt = 0; nt < 8; nt++) {
                tm_lo = fmaxf(tm_lo, fmaxf(cs[nt][0], cs[nt][1]));
                tm_hi = fmaxf(tm_hi, fmaxf(cs[nt][2], cs[nt][3]));
            }
            tm_lo = fmaxf(tm_lo, __shfl_xor_sync(0xffffffffu, tm_lo, 1));
            tm_lo = fmaxf(tm_lo, __shfl_xor_sync(0xffffffffu, tm_lo, 2));
            tm_hi = fmaxf(tm_hi, __shfl_xor_sync(0xffffffffu, tm_hi, 1));
            tm_hi = fmaxf(tm_hi, __shfl_xor_sync(0xffffffffu, tm_hi, 2));

            const float mn_lo = fmaxf(m_lo, tm_lo);
            const float mn_hi = fmaxf(m_hi, tm_hi);
            const float corr_lo = __expf(m_lo - mn_lo);
            const float corr_hi = __expf(m_hi - mn_hi);
            m_lo = mn_lo; m_hi = mn_hi;

            float rs_lo = 0.f, rs_hi = 0.f;
#pragma unroll
            for (int nt = 0; nt < 8; nt++) {
                cs[nt][0] = __expf(cs[nt][0] - mn_lo);
                cs[nt][1] = __expf(cs[nt][1] - mn_lo);
                cs[nt][2] = __expf(cs[nt][2] - mn_hi);
                cs[nt][3] = __expf(cs[nt][3] - mn_hi);
                rs_lo += cs[nt][0] + cs[nt][1];
                rs_hi += cs[nt][2] + cs[nt][3];
            }
            rs_lo += __shfl_xor_sync(0xffffffffu, rs_lo, 1);
            rs_lo += __shfl_xor_sync(0xffffffffu, rs_lo, 2);
            rs_hi += __shfl_xor_sync(0xffffffffu, rs_hi, 1);
            rs_hi += __shfl_xor_sync(0xffffffffu, rs_hi, 2);
            l_lo = l_lo * corr_lo + rs_lo;
            l_hi = l_hi * corr_hi + rs_hi;

#pragma unroll
            for (int nt = 0; nt < 8; nt++) {
                co[nt][0] *= corr_lo; co[nt][1] *= corr_lo;
                co[nt][2] *= corr_hi; co[nt][3] *= corr_hi;
            }

            // ---- O += P V : A-frag via quad shuffles, B-frag via ldmatrix --
#pragma unroll
            for (int ks = 0; ks < 8; ks++) {
                const float v00 = __shfl_sync(0xffffffffu, cs[ks][0], src0);
                const float v01 = __shfl_sync(0xffffffffu, cs[ks][1], src0);
                const float v10 = __shfl_sync(0xffffffffu, cs[ks][2], src0);
                const float v11 = __shfl_sync(0xffffffffu, cs[ks][3], src0);
                const float w00 = __shfl_sync(0xffffffffu, cs[ks][0], src1);
                const float w01 = __shfl_sync(0xffffffffu, cs[ks][1], src1);
                const float w10 = __shfl_sync(0xffffffffu, cs[ks][2], src1);
                const float w11 = __shfl_sync(0xffffffffu, cs[ks][3], src1);
                unsigned a[4];
                a[0] = f2tf(oddt ? v01 : v00);
                a[1] = f2tf(oddt ? v11 : v10);
                a[2] = f2tf(oddt ? w01 : w00);
                a[3] = f2tf(oddt ? w11 : w10);
#pragma unroll
                for (int j = 0; j < 4; j++) {
                    uint4 b;
                    ldsm4(b, vBase + j * (16 * AT_STRIDE * 4) + ks * 32);
                    mma8(co[2 * j    ], a, (const unsigned*)&b.x);
                    mma8(co[2 * j + 1], a, (const unsigned*)&b.z);
                }
            }
        }
    }

    // ---- store partials (unconditional, padded buffers) ----
    const int item  = blockIdx.x * HEADS + h;
    const int pbase = (z * NITEMS + item) * 128;
    if (t == 0) {
        g_pm[pbase + rb + g]     = m_lo;
        g_pl[pbase + rb + g]     = l_lo;
        g_pm[pbase + rb + g + 8] = m_hi;
        g_pl[pbase + rb + g + 8] = l_hi;
    }
#pragma unroll
    for (int nt = 0; nt < 8; nt++) {
        const int d = nt * 8 + t * 2;
        *(float2*)&g_po[(pbase + rb + g    ) * 64 + d] = make_float2(co[nt][0], co[nt][1]);
        *(float2*)&g_po[(pbase + rb + g + 8) * 64 + d] = make_float2(co[nt][2], co[nt][3]);
    }
#undef STAGE_KV
}

// ---------------- 4b) split-KV combine -> g_o (row-major) ------------------
__global__ __launch_bounds__(256)
void combine_kernel()
{
    const int item = blockIdx.x;           // qt*HEADS + h
    const int qt = item / HEADS, h = item % HEADS;
    const int tid = threadIdx.x;
    const int row = tid >> 1;              // 0..127
    const int d0 = (tid & 1) * 32;
    const int qg = qt * 128 + row;
    if (qg >= N_Q) return;

    const int pb = item * 128 + row;
    const float m0 = g_pm[pb];
    const float m1 = g_pm[NITEMS * 128 + pb];
    const float m2 = g_pm[2 * NITEMS * 128 + pb];
    const float mx = fmaxf(m0, fmaxf(m1, m2));
    const float w0 = __expf(m0 - mx);
    const float w1 = __expf(m1 - mx);
    const float w2 = __expf(m2 - mx);
    const float l = g_pl[pb] * w0 + g_pl[NITEMS * 128 + pb] * w1
                  + g_pl[2 * NITEMS * 128 + pb] * w2;
    const float inv = 1.0f / l;

    const float* p0 = g_po + (pb) * 64;
    const float* p1 = g_po + (NITEMS * 128 + pb) * 64;
    const float* p2 = g_po + (2 * NITEMS * 128 + pb) * 64;
    float* o = g_o + qg * CDIM + h * HDIM;
#pragma unroll
    for (int d = d0; d < d0 + 32; d += 4) {
        const float4 a = *(const float4*)(p0 + d);
        const float4 b = *(const float4*)(p1 + d);
        const float4 c = *(const float4*)(p2 + d);
        float4 r;
        r.x = (a.x * w0 + b.x * w1 + c.x * w2) * inv;
        r.y = (a.y * w0 + b.y * w1 + c.y * w2) * inv;
        r.z = (a.z * w0 + b.z * w1 + c.z * w2) * inv;
        r.w = (a.w * w0 + b.w * w1 + c.w * w2) * inv;
        *(float4*)(o + d) = r;
    }
}

// ---------------- launch ---------------------------------------------------
extern "C" void kernel_launch(void* const* d_in, const int* in_sizes, int n_in,
                              void* d_out, int out_size)
{
    const float* x          = (const float*)d_in[0];
    const float* pos        = (const float*)d_in[1];
    const float* mask       = (const float*)d_in[2];
    const float* mask_block = (const float*)d_in[3];
    const float* Wq         = (const float*)d_in[4];
    const float* Wk         = (const float*)d_in[5];
    const float* Wv         = (const float*)d_in[6];
    const float* Wp         = (const float*)d_in[7];
    const float* bp         = (const float*)d_in[8];
    float* out = (float*)d_out;

    cudaFuncSetAttribute(attn_tc, cudaFuncAttributeMaxDynamicSharedMemorySize, ATTN_SMEM);
    cudaFuncSetAttribute(proj_tc, cudaFuncAttributeMaxDynamicSharedMemorySize, PROJ_SMEM);

    pool_kernel<<<64, CDIM>>>(x, mask);
    scan_kernel<<<1, 1024>>>(mask, mask_block);   // also finalizes back token
    vzero_kernel<<<128, 256>>>();                 // zero Vt tail keys

    // fused Q/K/V projection: blockIdx.z = mode 0/1/2
    dim3 gqkv((N_Q + 127) / 128, CDIM / 64, 3);   // 33 x 6 x 3
    proj_tc<<<gqkv, 256, PROJ_SMEM>>>(0, x, pos, Wq, Wk, Wv, Wp, nullptr, nullptr);

    // split-KV attention + combine
    dim3 gattn((N_Q + 127) / 128, HEADS, NSPLIT); // 33 x 6 x 3
    attn_tc<<<gattn, 256, ATTN_SMEM>>>();
    combine_kernel<<<NITEMS, 256>>>();

    // output projection
    dim3 gout((N_Q + 127) / 128, CDIM / 64, 1);
    proj_tc<<<gout, 256, PROJ_SMEM>>>(3, x, pos, Wq, Wk, Wv, Wp, bp, out);
}

// round 15
// speedup vs baseline: 1.5672x; 1.0286x over previous
#include <cuda_runtime.h>
#include <cuda_bf16.h>
#include <math.h>

#define N_Q   4098
#define N_KV  4099
#define CDIM  384
#define HEADS 6
#define HDIM  64
#define NKV_PAD 4160                 // 65 * 64
#define ROWS_PAD 4224                // 33*128, proj A-tile padding
#define HSTR_VT (64 * NKV_PAD)       // per-head stride of transposed V
#define NITEMS 198                   // 33 qtiles * 6 heads
#define NSPLIT 3
#define WSTR (CDIM * CDIM)

// ---------------- scratch (device globals; allocation-free) ----------------
__device__ __align__(16) float g_pp[64 * CDIM];     // pooling partials
__device__ float  g_cntp[64];                       // count partials
__device__ __align__(16) float g_back[CDIM];        // back token
__device__ int    g_idx[N_KV];                      // kept key -> source row
__device__ int    g_M;                              // number of kept keys
__device__ __align__(16) float g_ax [ROWS_PAD * CDIM]; // tf32(x+pos)        (Q A)
__device__ __align__(16) float g_axk[ROWS_PAD * CDIM]; // tf32(kvx+pos)[idx] (K A)
__device__ __align__(16) float g_axv[ROWS_PAD * CDIM]; // tf32(kvx)[idx]     (V A)
__device__ __align__(16) float g_wt [4 * WSTR];        // tf32 weights q,k,v,p
__device__ __align__(16) float g_q[N_Q * CDIM];     // tf32, prescaled 1/8
__device__ __align__(16) float g_k[N_KV * CDIM];    // tf32
__device__ __align__(16) float g_vt[HEADS * HSTR_VT]; // V transposed, tf32
__device__ __align__(16) float g_o[ROWS_PAD * CDIM];  // tf32 (combine output)
// split-KV partials
__device__ __align__(16) float g_po[NSPLIT * NITEMS * 128 * 64];
__device__ float g_pm[NSPLIT * NITEMS * 128];
__device__ float g_pl[NSPLIT * NITEMS * 128];

// ---------------- helpers ---------------------------------------------------
__device__ __forceinline__ unsigned f2tf(float x)
{
    unsigned r;
    asm("cvt.rna.tf32.f32 %0, %1;" : "=r"(r) : "f"(x));
    return r;
}
__device__ __forceinline__ float f2tff(float x) { return __uint_as_float(f2tf(x)); }

__device__ __forceinline__ void mma8(float* c, const unsigned* a, const unsigned* b)
{
    asm volatile(
        "mma.sync.aligned.m16n8k8.row.col.f32.tf32.tf32.f32 "
        "{%0,%1,%2,%3}, {%4,%5,%6,%7}, {%8,%9}, {%0,%1,%2,%3};\n"
        : "+f"(c[0]), "+f"(c[1]), "+f"(c[2]), "+f"(c[3])
        : "r"(a[0]), "r"(a[1]), "r"(a[2]), "r"(a[3]), "r"(b[0]), "r"(b[1]));
}

__device__ __forceinline__ void ldsm4(uint4& d, unsigned addr)
{
    asm volatile("ldmatrix.sync.aligned.m8n8.x4.shared.b16 {%0,%1,%2,%3}, [%4];"
                 : "=r"(d.x), "=r"(d.y), "=r"(d.z), "=r"(d.w) : "r"(addr));
}

__device__ __forceinline__ void cp16(unsigned dst, const void* src, int sz)
{
    asm volatile("cp.async.ca.shared.global [%0], [%1], 16, %2;"
                 :: "r"(dst), "l"(src), "r"(sz));
}
__device__ __forceinline__ void cp16u(unsigned dst, const void* src)
{
    asm volatile("cp.async.ca.shared.global [%0], [%1], 16;"
                 :: "r"(dst), "l"(src));
}
#define CP_COMMIT() asm volatile("cp.async.commit_group;")
#define CP_WAIT(n)  asm volatile("cp.async.wait_group %0;" :: "n"(n))

// ---------------- 1) background pooling ------------------------------------
__global__ void pool_kernel(const float* __restrict__ x, const float* __restrict__ mask)
{
    const int c  = threadIdx.x;            // 384 threads
    const int n0 = blockIdx.x * 64;
    float s = 0.f;
#pragma unroll 8
    for (int i = 0; i < 64; i++) {
        const int n = n0 + i;
        const float rev = (mask[n] < 0.5f) ? 1.f : 0.f;
        s += rev * x[(1 + n) * CDIM + c];
    }
    g_pp[blockIdx.x * CDIM + c] = s;
    if (c == 0) {
        float cc = 0.f;
        for (int i = 0; i < 64; i++) cc += (mask[n0 + i] < 0.5f) ? 1.f : 0.f;
        g_cntp[blockIdx.x] = cc;
    }
}

// ---------------- 2) scan + back-token finalize (fused) --------------------
__global__ void scan_kernel(const float* __restrict__ mask,
                            const float* __restrict__ mask_block)
{
    __shared__ int sc[1024];
    const int t = threadIdx.x;

    if (t < CDIM) {
        float cnt = 0.f;
        for (int b = 0; b < 64; b++) cnt += g_cntp[b];
        float s = 0.f;
        for (int b = 0; b < 64; b++) s += g_pp[b * CDIM + t];
        g_back[t] = s / (cnt + 1e-10f);
    }

    const int base = t * 5;
    int flags[5];
    int cnt = 0;
#pragma unroll
    for (int e = 0; e < 5; e++) {
        int r = base + e;
        int f = 0;
        if (r < N_KV) {
            float mv = (r >= 1 && r <= N_Q - 2) ? mask[r - 1] : mask_block[r];
            f = (mv >= 0.5f) ? 1 : 0;
        }
        flags[e] = f;
        cnt += f;
    }
    sc[t] = cnt;
    __syncthreads();
    for (int off = 1; off < 1024; off <<= 1) {
        int v = (t >= off) ? sc[t - off] : 0;
        __syncthreads();
        sc[t] += v;
        __syncthreads();
    }
    int o = sc[t] - cnt;
#pragma unroll
    for (int e = 0; e < 5; e++)
        if (flags[e]) g_idx[o++] = base + e;
    if (t == 1023) g_M = sc[1023];
}

// ---------------- 2b) zero g_vt tail keys [g_M, NKV_PAD) -------------------
__global__ void vzero_kernel()
{
    const int M = g_M;
    const int tail = NKV_PAD - M;
    const int total = HEADS * 64 * tail;
    for (int i = blockIdx.x * blockDim.x + threadIdx.x; i < total;
         i += gridDim.x * blockDim.x) {
        const int row = i / tail;
        const int key = M + (i - row * tail);
        g_vt[row * NKV_PAD + key] = 0.f;
    }
}

// ---------------- 2c) prep: tf32 A-matrices for the projections ------------
// grid (4099, 3), 96 threads; job 0: Q rows, job 1: K gathered, job 2: V gathered
__global__ void prep_kernel(const float* __restrict__ x, const float* __restrict__ pos)
{
    const int row = blockIdx.x;
    const int job = blockIdx.y;
    const int c = threadIdx.x * 4;

    if (job == 0) {
        if (row >= N_Q) return;
        const float4 xv = *(const float4*)&x[row * CDIM + c];
        const float4 pv = *(const float4*)&pos[row * CDIM + c];
        float4 r = make_float4(f2tff(xv.x + pv.x), f2tff(xv.y + pv.y),
                               f2tff(xv.z + pv.z), f2tff(xv.w + pv.w));
        *(float4*)&g_ax[row * CDIM + c] = r;
    } else {
        if (row >= g_M) return;
        const int src = g_idx[row];
        const float4 bv = (src < N_Q) ? *(const float4*)&x[src * CDIM + c]
                                      : *(const float4*)&g_back[c];
        if (job == 1) {
            const float4 pv = *(const float4*)&pos[src * CDIM + c];
            float4 r = make_float4(f2tff(bv.x + pv.x), f2tff(bv.y + pv.y),
                                   f2tff(bv.z + pv.z), f2tff(bv.w + pv.w));
            *(float4*)&g_axk[row * CDIM + c] = r;
        } else {
            float4 r = make_float4(f2tff(bv.x), f2tff(bv.y), f2tff(bv.z), f2tff(bv.w));
            *(float4*)&g_axv[row * CDIM + c] = r;
        }
    }
}

// ---------------- 2d) prep: tf32 weight copies -----------------------------
// grid (144, 4), 256 threads (144*256 float4 = 147456 elems per matrix)
__global__ void wprep_kernel(const float* __restrict__ Wq, const float* __restrict__ Wk,
                             const float* __restrict__ Wv, const float* __restrict__ Wp)
{
    const int j = blockIdx.y;
    const float* src = (j == 0) ? Wq : (j == 1) ? Wk : (j == 2) ? Wv : Wp;
    const int e = (blockIdx.x * 256 + threadIdx.x) * 4;
    const float4 v = *(const float4*)&src[e];
    float4 r = make_float4(f2tff(v.x), f2tff(v.y), f2tff(v.z), f2tff(v.w));
    *(float4*)&g_wt[j * WSTR + e] = r;
}

// ---------------- 3) tf32 projection GEMM (cp.async + ldmatrix) ------------
// A-inputs are tf32-prerounded; staging is a pure byte copy.
// mode 0: g_ax  @ wt[0]^T * 1/8 -> g_q
// mode 1: g_axk @ wt[1]^T       -> g_k
// mode 2: g_axv @ wt[2]^T       -> g_vt (transposed store)
// mode 3: g_o   @ wt[3]^T + bp  -> d_out
#define PROJ_SMEM (2 * (128 * 36 + 64 * 36) * (int)sizeof(unsigned))

__global__ __launch_bounds__(256, 2)
void proj_tc(int base_mode, const float* __restrict__ bias,
             float* __restrict__ out_param)
{
    extern __shared__ unsigned smP[];

    const int mode = base_mode + blockIdx.z;
    const int rows = (mode == 1 || mode == 2) ? g_M : N_Q;
    const int m0 = blockIdx.x * 128;
    if (m0 >= rows) return;
    const int j0 = blockIdx.y * 64;

    const float* A = (mode == 0) ? g_ax : (mode == 1) ? g_axk
                   : (mode == 2) ? g_axv : g_o;
    const float* W = g_wt + mode * WSTR;
    float* outp = (mode == 0) ? g_q : (mode == 1) ? g_k : out_param;

    const int tid  = threadIdx.x;
    const int warp = tid >> 5, lane = tid & 31;
    const int wm = warp >> 1, wn = warp & 1;
    const int g = lane >> 2, t = lane & 3;
    const int m4 = lane >> 3, r8 = lane & 7;
    const unsigned smPB = (unsigned)__cvta_generic_to_shared(smP);

    // ldmatrix lane-base addresses (bytes); layouts match R12 (proven)
    const unsigned aA0 = smPB + ((wm * 32 + 8 * (m4 & 1) + r8) * 36) * 4u + (m4 >> 1) * 16u;
    const unsigned aW0 = smPB + (2 * 128 * 36 + (wn * 32 + 8 * (m4 >> 1) + r8) * 36) * 4u
                       + (m4 & 1) * 16u;

    // staging source/dst (row-major A[ROWS_PAD][384], W[384][384]; both in-bounds)
    const int rA = tid >> 3;               // 0..31 base; 4 chunks stride 32 rows? no:
    // A: 128 rows x 8 chunks = 1024 cp16; thread i covers lin = tid + k*256
    const int cA8 = (tid & 7) * 4;         // word offset within 32-word row

#define STAGE(kt, buf)                                                        \
    do {                                                                      \
        _Pragma("unroll")                                                     \
        for (int i = 0; i < 4; i++) {                                         \
            const int r = (tid + i * 256) >> 3;                               \
            cp16u(smPB + ((buf) * (128 * 36) + r * 36 + cA8) * 4u,            \
                  A + (m0 + r) * CDIM + (kt) + cA8);                          \
        }                                                                     \
        _Pragma("unroll")                                                     \
        for (int i = 0; i < 2; i++) {                                         \
            const int r = (tid + i * 256) >> 3;                               \
            cp16u(smPB + (2 * 128 * 36 + (buf) * (64 * 36) + r * 36 + cA8) * 4u, \
                  W + (j0 + r) * CDIM + (kt) + cA8);                          \
        }                                                                     \
    } while (0)

    float acc[2][4][4] = {};

    STAGE(0, 0);
    CP_COMMIT();

    const int NT = CDIM / 32;              // 12
    for (int kt = 0; kt < NT; kt++) {
        const int cur = kt & 1;
        __syncthreads();                   // buffer cur^1 free
        if (kt + 1 < NT) {
            STAGE((kt + 1) * 32, cur ^ 1);
            CP_COMMIT();
            CP_WAIT(1);
        } else {
            CP_WAIT(0);
        }
        __syncthreads();

        const unsigned aAb = aA0 + cur * (128 * 36 * 4);
        const unsigned aWb = aW0 + cur * (64 * 36 * 4);
#pragma unroll
        for (int ks = 0; ks < 4; ks++) {
            uint4 av[2], bv[2];
#pragma unroll
            for (int mt = 0; mt < 2; mt++)
                ldsm4(av[mt], aAb + mt * (16 * 36 * 4) + ks * 32);
#pragma unroll
            for (int np = 0; np < 2; np++)
                ldsm4(bv[np], aWb + np * (16 * 36 * 4) + ks * 32);
#pragma unroll
            for (int mt = 0; mt < 2; mt++)
#pragma unroll
                for (int np = 0; np < 2; np++) {
                    mma8(acc[mt][2 * np    ], (const unsigned*)&av[mt], (const unsigned*)&bv[np].x);
                    mma8(acc[mt][2 * np + 1], (const unsigned*)&av[mt], (const unsigned*)&bv[np].z);
                }
        }
    }

#pragma unroll
    for (int mt = 0; mt < 2; mt++) {
#pragma unroll
        for (int nt = 0; nt < 4; nt++) {
            const int col = j0 + wn * 32 + nt * 8 + t * 2;
            const int r0 = m0 + wm * 32 + mt * 16 + g;
            const int r1 = r0 + 8;
            float* a = acc[mt][nt];
            if (mode == 3) {
                const float b0 = bias ? bias[col]     : 0.f;
                const float b1 = bias ? bias[col + 1] : 0.f;
                if (r0 < rows)
                    *(float2*)&outp[r0 * CDIM + col] = make_float2(a[0] + b0, a[1] + b1);
                if (r1 < rows)
                    *(float2*)&outp[r1 * CDIM + col] = make_float2(a[2] + b0, a[3] + b1);
            } else if (mode == 2) {
                float* vb = g_vt + (col >> 6) * HSTR_VT + (col & 63) * NKV_PAD;
                if (r0 < rows) {
                    vb[r0]           = f2tff(a[0]);
                    vb[NKV_PAD + r0] = f2tff(a[1]);
                }
                if (r1 < rows) {
                    vb[r1]           = f2tff(a[2]);
                    vb[NKV_PAD + r1] = f2tff(a[3]);
                }
            } else {
                const float oscale = (mode == 0) ? 0.125f : 1.0f;
                if (r0 < rows) {
                    float2 v = make_float2(f2tff(a[0] * oscale), f2tff(a[1] * oscale));
                    *(float2*)&outp[r0 * CDIM + col] = v;
                }
                if (r1 < rows) {
                    float2 v = make_float2(f2tff(a[2] * oscale), f2tff(a[3] * oscale));
                    *(float2*)&outp[r1 * CDIM + col] = v;
                }
            }
        }
    }
#undef STAGE
}

// ---------------- 4) tf32 flash attention (split-KV, all-ldmatrix) ---------
#define AT_STRIDE 68
#define K_OFF  8704
#define VT_OFF 17408
#define KV_BUF 4352
#define ATTN_SMEM ((VT_OFF + 2 * KV_BUF) * (int)sizeof(unsigned))

__global__ __launch_bounds__(256, 2)
void attn_tc()
{
    extern __shared__ unsigned sm[];

    const int h  = blockIdx.y;
    const int q0 = blockIdx.x * 128;
    const int z  = blockIdx.z;
    const int M  = g_M;
    const int nT = (M + 63) >> 6;
    const int per = (nT + NSPLIT - 1) / NSPLIT;
    const int t0 = z * per;
    const int t1 = min(nT, t0 + per);

    const int tid = threadIdx.x, warp = tid >> 5, lane = tid & 31;
    const int g = lane >> 2, t = lane & 3;
    const int rb = warp * 16;
    const int m4 = lane >> 3, r8 = lane & 7;
    const unsigned smB = (unsigned)__cvta_generic_to_shared(sm);

    const unsigned aQ  = smB + ((rb + 8 * (m4 & 1) + r8) * AT_STRIDE) * 4u + (m4 >> 1) * 16u;
    const unsigned aKc = ((8 * (m4 >> 1) + r8) * AT_STRIDE) * 4u + (m4 & 1) * 16u;
    const int src0 = (lane & 28) | (t >> 1);
    const int src1 = src0 + 2;
    const bool oddt = (t & 1);

#define STAGE_KV(kt, buf)                                                     \
    do {                                                                      \
        const float* vsrc = g_vt + h * HSTR_VT + (kt) * 64;                   \
        _Pragma("unroll")                                                     \
        for (int i = 0; i < 4; i++) {                                         \
            const int lin = tid + i * 256;                                    \
            const int r = lin >> 4, c4 = (lin & 15) * 4;                      \
            const int kg = (kt) * 64 + r;                                     \
            cp16(smB + ((K_OFF + (buf) * KV_BUF) + r * AT_STRIDE + c4) * 4u,  \
                 &g_k[kg * CDIM + h * HDIM + c4], (kg < M) ? 16 : 0);         \
            cp16u(smB + ((VT_OFF + (buf) * KV_BUF) + r * AT_STRIDE + c4) * 4u,\
                  vsrc + r * NKV_PAD + c4);                                   \
        }                                                                     \
    } while (0)

    float m_lo = -1e30f, m_hi = -1e30f, l_lo = 0.f, l_hi = 0.f;
    float co[8][4] = {};

    if (t0 < t1) {
#pragma unroll
        for (int i = 0; i < 8; i++) {
            const int lin = tid + i * 256;
            const int r = lin >> 4, c4 = (lin & 15) * 4;
            cp16(smB + (r * AT_STRIDE + c4) * 4u,
                 &g_q[(q0 + r) * CDIM + h * HDIM + c4],
                 (q0 + r < N_Q) ? 16 : 0);
        }
        STAGE_KV(t0, 0);
        CP_COMMIT();

        for (int kt = t0; kt < t1; kt++) {
            const int cur = (kt - t0) & 1;
            __syncthreads();
            if (kt + 1 < t1) {
                STAGE_KV(kt + 1, cur ^ 1);
                CP_COMMIT();
                CP_WAIT(1);
            } else {
                CP_WAIT(0);
            }
            __syncthreads();

            const unsigned kBase = smB + (K_OFF  + cur * KV_BUF) * 4u + aKc;
            const unsigned vBase = smB + (VT_OFF + cur * KV_BUF) * 4u + aKc;

            float cs[8][4] = {};
#pragma unroll
            for (int ks = 0; ks < 8; ks++) {
                uint4 a;
                ldsm4(a, aQ + ks * 32);
#pragma unroll
                for (int j = 0; j < 4; j++) {
                    uint4 b;
                    ldsm4(b, kBase + j * (16 * AT_STRIDE * 4) + ks * 32);
                    mma8(cs[2 * j    ], (const unsigned*)&a, (const unsigned*)&b.x);
                    mma8(cs[2 * j + 1], (const unsigned*)&a, (const unsigned*)&b.z);
                }
            }

            if (kt == nT - 1) {
#pragma unroll
                for (int nt = 0; nt < 8; nt++) {
                    const int c0 = kt * 64 + nt * 8 + t * 2;
                    if (c0     >= M) { cs[nt][0] = -1e30f; cs[nt][2] = -1e30f; }
                    if (c0 + 1 >= M) { cs[nt][1] = -1e30f; cs[nt][3] = -1e30f; }
                }
            }
            float tm_lo = -1e30f, tm_hi = -1e30f;
#pragma unroll
            for (int nt = 0; nt < 8; nt++) {
                tm_lo = fmaxf(tm_lo, fmaxf(cs[nt][0], cs[nt][1]));
                tm_hi = fmaxf(tm_hi, fmaxf(cs[nt][2], cs[nt][3]));
            }
            tm_lo = fmaxf(tm_lo, __shfl_xor_sync(0xffffffffu, tm_lo, 1));
            tm_lo = fmaxf(tm_lo, __shfl_xor_sync(0xffffffffu, tm_lo, 2));
            tm_hi = fmaxf(tm_hi, __shfl_xor_sync(0xffffffffu, tm_hi, 1));
            tm_hi = fmaxf(tm_hi, __shfl_xor_sync(0xffffffffu, tm_hi, 2));

            const float mn_lo = fmaxf(m_lo, tm_lo);
            const float mn_hi = fmaxf(m_hi, tm_hi);
            const float corr_lo = __expf(m_lo - mn_lo);
            const float corr_hi = __expf(m_hi - mn_hi);
            m_lo = mn_lo; m_hi = mn_hi;

            float rs_lo = 0.f, rs_hi = 0.f;
#pragma unroll
            for (int nt = 0; nt < 8; nt++) {
                cs[nt][0] = __expf(cs[nt][0] - mn_lo);
                cs[nt][1] = __expf(cs[nt][1] - mn_lo);
                cs[nt][2] = __expf(cs[nt][2] - mn_hi);
                cs[nt][3] = __expf(cs[nt][3] - mn_hi);
                rs_lo += cs[nt][0] + cs[nt][1];
                rs_hi += cs[nt][2] + cs[nt][3];
            }
            rs_lo += __shfl_xor_sync(0xffffffffu, rs_lo, 1);
            rs_lo += __shfl_xor_sync(0xffffffffu, rs_lo, 2);
            rs_hi += __shfl_xor_sync(0xffffffffu, rs_hi, 1);
            rs_hi += __shfl_xor_sync(0xffffffffu, rs_hi, 2);
            l_lo = l_lo * corr_lo + rs_lo;
            l_hi = l_hi * corr_hi + rs_hi;

#pragma unroll
            for (int nt = 0; nt < 8; nt++) {
                co[nt][0] *= corr_lo; co[nt][1] *= corr_lo;
                co[nt][2] *= corr_hi; co[nt][3] *= corr_hi;
            }

#pragma unroll
            for (int ks = 0; ks < 8; ks++) {
                const float v00 = __shfl_sync(0xffffffffu, cs[ks][0], src0);
                const float v01 = __shfl_sync(0xffffffffu, cs[ks][1], src0);
                const float v10 = __shfl_sync(0xffffffffu, cs[ks][2], src0);
                const float v11 = __shfl_sync(0xffffffffu, cs[ks][3], src0);
                const float w00 = __shfl_sync(0xffffffffu, cs[ks][0], src1);
                const float w01 = __shfl_sync(0xffffffffu, cs[ks][1], src1);
                const float w10 = __shfl_sync(0xffffffffu, cs[ks][2], src1);
                const float w11 = __shfl_sync(0xffffffffu, cs[ks][3], src1);
                unsigned a[4];
                a[0] = f2tf(oddt ? v01 : v00);
                a[1] = f2tf(oddt ? v11 : v10);
                a[2] = f2tf(oddt ? w01 : w00);
                a[3] = f2tf(oddt ? w11 : w10);
#pragma unroll
                for (int j = 0; j < 4; j++) {
                    uint4 b;
                    ldsm4(b, vBase + j * (16 * AT_STRIDE * 4) + ks * 32);
                    mma8(co[2 * j    ], a, (const unsigned*)&b.x);
                    mma8(co[2 * j + 1], a, (const unsigned*)&b.z);
                }
            }
        }
    }

    // ---- store partials ----
    const int item  = blockIdx.x * HEADS + h;
    const int pbase = (z * NITEMS + item) * 128;
    if (t == 0) {
        g_pm[pbase + rb + g]     = m_lo;
        g_pl[pbase + rb + g]     = l_lo;
        g_pm[pbase + rb + g + 8] = m_hi;
        g_pl[pbase + rb + g + 8] = l_hi;
    }
#pragma unroll
    for (int nt = 0; nt < 8; nt++) {
        const int d = nt * 8 + t * 2;
        *(float2*)&g_po[(pbase + rb + g    ) * 64 + d] = make_float2(co[nt][0], co[nt][1]);
        *(float2*)&g_po[(pbase + rb + g + 8) * 64 + d] = make_float2(co[nt][2], co[nt][3]);
    }
#undef STAGE_KV
}

// ---------------- 4b) split-KV combine -> g_o (tf32-rounded) ---------------
__global__ __launch_bounds__(256)
void combine_kernel()
{
    const int item = blockIdx.x;           // qt*HEADS + h
    const int qt = item / HEADS, h = item % HEADS;
    const int tid = threadIdx.x;
    const int row = tid >> 1;              // 0..127
    const int d0 = (tid & 1) * 32;
    const int qg = qt * 128 + row;
    if (qg >= N_Q) return;

    const int pb = item * 128 + row;
    const float m0 = g_pm[pb];
    const float m1 = g_pm[NITEMS * 128 + pb];
    const float m2 = g_pm[2 * NITEMS * 128 + pb];
    const float mx = fmaxf(m0, fmaxf(m1, m2));
    const float w0 = __expf(m0 - mx);
    const float w1 = __expf(m1 - mx);
    const float w2 = __expf(m2 - mx);
    const float l = g_pl[pb] * w0 + g_pl[NITEMS * 128 + pb] * w1
                  + g_pl[2 * NITEMS * 128 + pb] * w2;
    const float inv = 1.0f / l;

    const float* p0 = g_po + (pb) * 64;
    const float* p1 = g_po + (NITEMS * 128 + pb) * 64;
    const float* p2 = g_po + (2 * NITEMS * 128 + pb) * 64;
    float* o = g_o + qg * CDIM + h * HDIM;
#pragma unroll
    for (int d = d0; d < d0 + 32; d += 4) {
        const float4 a = *(const float4*)(p0 + d);
        const float4 b = *(const float4*)(p1 + d);
        const float4 c = *(const float4*)(p2 + d);
        float4 r;
        r.x = f2tff((a.x * w0 + b.x * w1 + c.x * w2) * inv);
        r.y = f2tff((a.y * w0 + b.y * w1 + c.y * w2) * inv);
        r.z = f2tff((a.z * w0 + b.z * w1 + c.z * w2) * inv);
        r.w = f2tff((a.w * w0 + b.w * w1 + c.w * w2) * inv);
        *(float4*)(o + d) = r;
    }
}

// ---------------- launch ---------------------------------------------------
extern "C" void kernel_launch(void* const* d_in, const int* in_sizes, int n_in,
                              void* d_out, int out_size)
{
    const float* x          = (const float*)d_in[0];
    const float* pos        = (const float*)d_in[1];
    const float* mask       = (const float*)d_in[2];
    const float* mask_block = (const float*)d_in[3];
    const float* Wq         = (const float*)d_in[4];
    const float* Wk         = (const float*)d_in[5];
    const float* Wv         = (const float*)d_in[6];
    const float* Wp         = (const float*)d_in[7];
    const float* bp         = (const float*)d_in[8];
    float* out = (float*)d_out;

    cudaFuncSetAttribute(attn_tc, cudaFuncAttributeMaxDynamicSharedMemorySize, ATTN_SMEM);
    cudaFuncSetAttribute(proj_tc, cudaFuncAttributeMaxDynamicSharedMemorySize, PROJ_SMEM);

    pool_kernel<<<64, CDIM>>>(x, mask);
    scan_kernel<<<1, 1024>>>(mask, mask_block);   // also finalizes back token
    vzero_kernel<<<128, 256>>>();                 // zero Vt tail keys
    wprep_kernel<<<dim3(144, 4), 256>>>(Wq, Wk, Wv, Wp);
    prep_kernel<<<dim3(N_KV, 3), 96>>>(x, pos);   // tf32 A-matrices (uses scan output)

    // fused Q/K/V projection: blockIdx.z = mode 0/1/2
    dim3 gqkv((N_Q + 127) / 128, CDIM / 64, 3);   // 33 x 6 x 3
    proj_tc<<<gqkv, 256, PROJ_SMEM>>>(0, nullptr, nullptr);

    // split-KV attention + combine
    dim3 gattn((N_Q + 127) / 128, HEADS, NSPLIT); // 33 x 6 x 3
    attn_tc<<<gattn, 256, ATTN_SMEM>>>();
    combine_kernel<<<NITEMS, 256>>>();

    // output projection
    dim3 gout((N_Q + 127) / 128, CDIM / 64, 1);
    proj_tc<<<gout, 256, PROJ_SMEM>>>(3, bp, out);
}